// round 6
// baseline (speedup 1.0000x reference)
#include <cuda_runtime.h>
#include <cuda_fp16.h>
#include <math.h>
#include <stdint.h>

#define BB 16
#define TT 128
#define HH 1024
#define EE 1024
#define VV 32000
#define KK 2048

#define NB 128                        // persistent grid blocks (<=148, 1/SM)
#define NT 256

// ---- phase A (LSTM) ----
#define L_ROWS 32
#define L_NCHUNK 32
#define XPAD 2056
#define LWPAD 72
#define XHI_OFF  0
#define XLO_OFF  65792
#define LWH0_OFF 131584
#define LWL0_OFF 136192
#define LWH1_OFF 140800
#define LWL1_OFF 145408
#define G4_OFF   150016
#define RED_OFF  152192
#define TOK_OFF  154240
#define L_SMEM   154304

// ---- phase B (logits) ----
#define K2_BLOCKS 250                 // pexp chunks (125 blocks x 2 passes)
#define NCHUNK 16
#define TAU 0.05f
#define WPAD 72
#define HPAD 1032
#define LPAD 17
#define H_OFF    0
#define W0_OFF   33024
#define W1_OFF   51456
#define LOG_OFF  69888
#define THR_OFF  78592
#define CNT_OFF  78656
#define CAND_OFF 78672

// -------- persistent scratch --------
__device__ float  g_h[2][BB * HH];
__device__ float  g_c[BB * HH];
__device__ __half g_h16[BB * HH];                // hi plane of h (also logits input)
__device__ __half g_hlo[BB * HH];                // lo plane of h
__device__ __half g_W16[(size_t)VV * HH];
__device__ __half g_Whi[(size_t)4 * HH * KK];
__device__ __half g_Wlo[(size_t)4 * HH * KK];
__device__ float  g_pb[4 * HH];
__device__ unsigned long long g_amax[2][BB];
__device__ unsigned g_approx[2][BB];
__device__ float  g_pexp[TT][BB][K2_BLOCKS];
__device__ volatile unsigned g_bar_gen;
__device__ unsigned g_bar_cnt;

// ---------------- helpers ----------------
__device__ __forceinline__ unsigned ford(float f) {
    unsigned u = __float_as_uint(f);
    return (u & 0x80000000u) ? ~u : (u | 0x80000000u);
}
__device__ __forceinline__ float funord(unsigned v) {
    unsigned bits = (v & 0x80000000u) ? (v ^ 0x80000000u) : ~v;
    return __uint_as_float(bits);
}
#define CP16(dst, src)  asm volatile("cp.async.cg.shared.global [%0], [%1], 16;" :: "r"(dst), "l"(src) : "memory")
#define CP_COMMIT()     asm volatile("cp.async.commit_group;" ::: "memory")
#define CP_WAIT1()      asm volatile("cp.async.wait_group 1;" ::: "memory")
#define CP_WAIT0()      asm volatile("cp.async.wait_group 0;" ::: "memory")

__device__ __forceinline__ uint32_t smem_u32(const void* p) {
    uint32_t a;
    asm("{ .reg .u64 t; cvta.to.shared.u64 t, %1; cvt.u32.u64 %0, t; }" : "=r"(a) : "l"(p));
    return a;
}
__device__ __forceinline__ void mma16816(float* c, uint32_t a0, uint32_t a1,
                                         uint32_t a2, uint32_t a3,
                                         uint32_t b0, uint32_t b1) {
    asm volatile(
        "mma.sync.aligned.m16n8k16.row.col.f32.f16.f16.f32 "
        "{%0,%1,%2,%3}, {%4,%5,%6,%7}, {%8,%9}, {%0,%1,%2,%3};"
        : "+f"(c[0]), "+f"(c[1]), "+f"(c[2]), "+f"(c[3])
        : "r"(a0), "r"(a1), "r"(a2), "r"(a3), "r"(b0), "r"(b1));
}

// grid barrier: monotonic counter (no reset race), generation flag release.
__device__ __forceinline__ void grid_bar() {
    __syncthreads();
    if (threadIdx.x == 0) {
        __threadfence();
        unsigned gen = g_bar_gen;
        unsigned t = atomicAdd(&g_bar_cnt, 1u) + 1u;
        if ((t & (NB - 1)) == 0) {           // NB-th arrival of this instance
            __threadfence();
            g_bar_gen = gen + 1u;
        } else {
            while (g_bar_gen == gen) { __nanosleep(64); }
            __threadfence();
        }
    }
    __syncthreads();
}

// ---------------------------------------------------------------------
__global__ void k_init(const float* __restrict__ h0, const float* __restrict__ c0,
                       const float* __restrict__ bih, const float* __restrict__ bhh) {
    int i = blockIdx.x * blockDim.x + threadIdx.x;
    if (i < BB * HH) {
        float h = h0[i];
        g_h[0][i] = h;
        g_c[i]    = c0[i];
        __half hh = __float2half_rn(h);
        g_h16[i] = hh;
        g_hlo[i] = __float2half_rn(h - __half2float(hh));
    }
    if (i < BB) g_amax[0][i] = (unsigned long long)(~1u);   // SOS = 1
    if (i < 4 * HH) {
        int j = i >> 2, g = i & 3;
        int orig = g * HH + j;
        g_pb[i] = bih[orig] + bhh[orig];
    }
}

__global__ void k_cvt(const float* __restrict__ W) {
    size_t i = ((size_t)blockIdx.x * 256 + threadIdx.x) * 8;
    float4 a = *(const float4*)(W + i);
    float4 b = *(const float4*)(W + i + 4);
    __half2 p0 = __floats2half2_rn(a.x, a.y), p1 = __floats2half2_rn(a.z, a.w);
    __half2 p2 = __floats2half2_rn(b.x, b.y), p3 = __floats2half2_rn(b.z, b.w);
    uint4 o;
    o.x = *(uint32_t*)&p0; o.y = *(uint32_t*)&p1;
    o.z = *(uint32_t*)&p2; o.w = *(uint32_t*)&p3;
    *(uint4*)(g_W16 + i) = o;
}

__global__ void k_cvt2(const float* __restrict__ Wih, const float* __restrict__ Whh) {
    size_t idx = ((size_t)blockIdx.x * 256 + threadIdx.x) * 8;
    int nr = (int)(idx >> 11);
    int k  = (int)(idx & 2047);
    int j = nr >> 2, g = nr & 3;
    int orig = g * HH + j;
    const float* src = (k < HH) ? (Wih + (size_t)orig * HH + k)
                                : (Whh + (size_t)orig * HH + (k - HH));
    __half hi8[8], lo8[8];
#pragma unroll
    for (int q = 0; q < 8; q++) {
        float v = src[q];
        __half h = __float2half_rn(v);
        hi8[q] = h;
        lo8[q] = __float2half_rn(v - __half2float(h));
    }
    *(uint4*)(g_Whi + idx) = *(uint4*)hi8;
    *(uint4*)(g_Wlo + idx) = *(uint4*)lo8;
}

// ---------------------------------------------------------------------
// Persistent decode: 128 steps, 2 phases + 2 grid barriers per step.
__global__ void __launch_bounds__(NT)
k_decode(const float* __restrict__ emb,
         const float* __restrict__ Wlin, const float* __restrict__ blin,
         float* __restrict__ out) {
    extern __shared__ char sm[];
    const uint32_t smem_base = smem_u32(sm);
    const int tid = threadIdx.x, warp = tid >> 5, lane = tid & 31;
    const int r = lane >> 2, q4 = lane & 3;

    for (int t = 0; t < TT; t++) {
        const int pr  = t & 1;
        const int cur = (t + 1) & 1;

        // ============== PHASE A: LSTM step ==============
        {
            __half* xhi = (__half*)(sm + XHI_OFF);
            __half* xlo = (__half*)(sm + XLO_OFF);
            float*  g4  = (float*)(sm + G4_OFF);
            float*  red = (float*)(sm + RED_OFF);
            int*    tok_s = (int*)(sm + TOK_OFF);

            const int quad = warp & 3, kh = warp >> 2;
            const int mrow_base = (quad >> 1) * 16;
            const int nb_base   = (quad & 1) * 8;

            if (tid < BB) tok_s[tid] = (int)(~(unsigned)g_amax[pr][tid]);
            if (blockIdx.x == 0 && tid < BB) { g_amax[cur][tid] = 0ull; g_approx[cur][tid] = 0u; }
            __syncthreads();

            // group 0: h-half hi/lo planes via cp.async
#pragma unroll
            for (int q = 0; q < 8; q++) {
                int i = tid + q * 256;
                int b = i >> 7, k8 = i & 127;
                CP16(smem_base + XHI_OFF + (uint32_t)(b * XPAD + 1024 + k8 * 8) * 2,
                     g_h16 + b * HH + k8 * 8);
                CP16(smem_base + XLO_OFF + (uint32_t)(b * XPAD + 1024 + k8 * 8) * 2,
                     g_hlo + b * HH + k8 * 8);
            }
            CP_COMMIT();

            // group 1: W chunk 0
            const size_t wbase = (size_t)blockIdx.x * L_ROWS * KK;
            {
                int row = tid >> 3, col16 = tid & 7;
                size_t src = wbase + (size_t)row * KK + col16 * 8;
                CP16(smem_base + LWH0_OFF + (uint32_t)(row * LWPAD + col16 * 8) * 2, g_Whi + src);
                CP16(smem_base + LWL0_OFF + (uint32_t)(row * LWPAD + col16 * 8) * 2, g_Wlo + src);
            }
            CP_COMMIT();

            // emb half: gather + split (redundant per block, L2-hot)
#pragma unroll
            for (int q = 0; q < 16; q++) {
                int i4 = tid + q * 256;
                int b = i4 >> 8, k = (i4 & 255) << 2;
                float4 v = *(const float4*)(emb + (size_t)tok_s[b] * EE + k);
                __half h0 = __float2half_rn(v.x), h1 = __float2half_rn(v.y);
                __half h2 = __float2half_rn(v.z), h3 = __float2half_rn(v.w);
                __half l0 = __float2half_rn(v.x - __half2float(h0));
                __half l1 = __float2half_rn(v.y - __half2float(h1));
                __half l2 = __float2half_rn(v.z - __half2float(h2));
                __half l3 = __float2half_rn(v.w - __half2float(h3));
                __half hi4[4] = {h0, h1, h2, h3};
                __half lo4[4] = {l0, l1, l2, l3};
                *(uint2*)(xhi + b * XPAD + k) = *(uint2*)hi4;
                *(uint2*)(xlo + b * XPAD + k) = *(uint2*)lo4;
            }

            float acc[4] = {0.f, 0.f, 0.f, 0.f};

            for (int c = 0; c < L_NCHUNK; c++) {
                if (c + 1 < L_NCHUNK) {
                    uint32_t oh = ((c + 1) & 1) ? LWH1_OFF : LWH0_OFF;
                    uint32_t ol = ((c + 1) & 1) ? LWL1_OFF : LWL0_OFF;
                    int row = tid >> 3, col16 = tid & 7;
                    size_t src = wbase + (size_t)row * KK + (c + 1) * 64 + col16 * 8;
                    CP16(smem_base + oh + (uint32_t)(row * LWPAD + col16 * 8) * 2, g_Whi + src);
                    CP16(smem_base + ol + (uint32_t)(row * LWPAD + col16 * 8) * 2, g_Wlo + src);
                    CP_COMMIT();
                    CP_WAIT1();
                } else {
                    CP_WAIT0();
                }
                __syncthreads();

                const __half* wh = (const __half*)(sm + ((c & 1) ? LWH1_OFF : LWH0_OFF));
                const __half* wl = (const __half*)(sm + ((c & 1) ? LWL1_OFF : LWL0_OFF));
#pragma unroll
                for (int ks = 0; ks < 2; ks++) {
                    int k_local = kh * 32 + ks * 16 + q4 * 2;
                    int kg = c * 64 + k_local;
                    const int ra = (mrow_base + r) * LWPAD;
                    const int rb = (mrow_base + r + 8) * LWPAD;
                    uint32_t ah0 = *(const uint32_t*)(wh + ra + k_local);
                    uint32_t ah1 = *(const uint32_t*)(wh + rb + k_local);
                    uint32_t ah2 = *(const uint32_t*)(wh + ra + k_local + 8);
                    uint32_t ah3 = *(const uint32_t*)(wh + rb + k_local + 8);
                    uint32_t al0 = *(const uint32_t*)(wl + ra + k_local);
                    uint32_t al1 = *(const uint32_t*)(wl + rb + k_local);
                    uint32_t al2 = *(const uint32_t*)(wl + ra + k_local + 8);
                    uint32_t al3 = *(const uint32_t*)(wl + rb + k_local + 8);

                    const int xb = (nb_base + r) * XPAD;
                    uint32_t bh0 = *(const uint32_t*)(xhi + xb + kg);
                    uint32_t bh1 = *(const uint32_t*)(xhi + xb + kg + 8);
                    uint32_t bl0 = *(const uint32_t*)(xlo + xb + kg);
                    uint32_t bl1 = *(const uint32_t*)(xlo + xb + kg + 8);

                    mma16816(acc, ah0, ah1, ah2, ah3, bh0, bh1);
                    mma16816(acc, ah0, ah1, ah2, ah3, bl0, bl1);
                    mma16816(acc, al0, al1, al2, al3, bh0, bh1);
                }
                __syncthreads();
            }

            const int kh_l = warp >> 2;
            if (kh_l == 1) {
                float* dst = red + ((warp & 3) * 32 + lane) * 4;
                dst[0] = acc[0]; dst[1] = acc[1]; dst[2] = acc[2]; dst[3] = acc[3];
            }
            __syncthreads();
            if (kh_l == 0) {
                const float* srcv = red + ((warp & 3) * 32 + lane) * 4;
                acc[0] += srcv[0]; acc[1] += srcv[1]; acc[2] += srcv[2]; acc[3] += srcv[3];
                int row0 = mrow_base + r;
                int col = nb_base + q4 * 2;
                g4[row0 * 17 + col]           = acc[0];
                g4[row0 * 17 + col + 1]       = acc[1];
                g4[(row0 + 8) * 17 + col]     = acc[2];
                g4[(row0 + 8) * 17 + col + 1] = acc[3];
            }
            __syncthreads();

            if (tid < 128) {
                int unitloc = tid >> 4, b = tid & 15;
                int lr = unitloc * 4;
                int nrb = blockIdx.x * L_ROWS + lr;
                float gi = g4[(lr + 0) * 17 + b] + g_pb[nrb + 0];
                float gf = g4[(lr + 1) * 17 + b] + g_pb[nrb + 1];
                float gg = g4[(lr + 2) * 17 + b] + g_pb[nrb + 2];
                float go = g4[(lr + 3) * 17 + b] + g_pb[nrb + 3];
                int j = blockIdx.x * 8 + unitloc;
                float si = 1.f / (1.f + expf(-gi));
                float sf = 1.f / (1.f + expf(-gf));
                float so = 1.f / (1.f + expf(-go));
                float cc = sf * g_c[b * HH + j] + si * tanhf(gg);
                g_c[b * HH + j] = cc;
                float h = so * tanhf(cc);
                g_h[cur][b * HH + j] = h;
                __half hh = __float2half_rn(h);
                g_h16[b * HH + j] = hh;
                g_hlo[b * HH + j] = __float2half_rn(h - __half2float(hh));
            }
        }

        grid_bar();   // h / h16 / hlo / amax-reset visible chip-wide

        // ============== PHASE B: logits (125 blocks x 2 passes) ==============
        if (blockIdx.x < 125) {
            __half* h_s   = (__half*)(sm + H_OFF);
            float*  log_s = (float*)(sm + LOG_OFF);
            float*  thr_s = (float*)(sm + THR_OFF);
            int*    cnt_s = (int*)(sm + CNT_OFF);
            int*    cand_s = (int*)(sm + CAND_OFF);

            // load h16 once
#pragma unroll
            for (int q = 0; q < 8; q++) {
                int i = tid + q * 256;
                int b = i >> 7, k8 = i & 127;
                float4 v = *(const float4*)(g_h16 + (size_t)b * HH + k8 * 8);
                *(float4*)(h_s + b * HPAD + k8 * 8) = v;
            }

            for (int p = 0; p < 2; p++) {
                if (tid == 0) *cnt_s = 0;

                const int rows_base = blockIdx.x * 256 + p * 128;
                const int chunk = blockIdx.x * 2 + p;
                const size_t wrow_base = (size_t)rows_base * HH;
#pragma unroll
                for (int qq = 0; qq < 4; qq++) {
                    int i = tid + qq * 256;
                    int row = i >> 3, col16 = i & 7;
                    CP16(smem_base + W0_OFF + (uint32_t)(row * WPAD + col16 * 8) * 2,
                         g_W16 + wrow_base + (size_t)row * HH + col16 * 8);
                }
                CP_COMMIT();

                float acc0[4] = {0.f, 0.f, 0.f, 0.f};
                float acc1[4] = {0.f, 0.f, 0.f, 0.f};

                for (int c = 0; c < NCHUNK; c++) {
                    if (c + 1 < NCHUNK) {
                        uint32_t wb_off = ((c + 1) & 1) ? W1_OFF : W0_OFF;
#pragma unroll
                        for (int qq = 0; qq < 4; qq++) {
                            int i = tid + qq * 256;
                            int row = i >> 3, col16 = i & 7;
                            CP16(smem_base + wb_off + (uint32_t)(row * WPAD + col16 * 8) * 2,
                                 g_W16 + wrow_base + (size_t)row * HH + (c + 1) * 64 + col16 * 8);
                        }
                        CP_COMMIT();
                        CP_WAIT1();
                    } else {
                        CP_WAIT0();
                    }
                    __syncthreads();

                    const __half* wb = (const __half*)(sm + ((c & 1) ? W1_OFF : W0_OFF));
                    const int kbase = c * 64;
#pragma unroll
                    for (int ks = 0; ks < 4; ks++) {
                        int k0 = ks * 16 + q4 * 2;
                        uint32_t a0 = *(const uint32_t*)(wb + (warp * 16 + r) * WPAD + k0);
                        uint32_t a1 = *(const uint32_t*)(wb + (warp * 16 + r + 8) * WPAD + k0);
                        uint32_t a2 = *(const uint32_t*)(wb + (warp * 16 + r) * WPAD + k0 + 8);
                        uint32_t a3 = *(const uint32_t*)(wb + (warp * 16 + r + 8) * WPAD + k0 + 8);
                        int kg = kbase + k0;
                        uint32_t b00 = *(const uint32_t*)(h_s + r * HPAD + kg);
                        uint32_t b01 = *(const uint32_t*)(h_s + r * HPAD + kg + 8);
                        uint32_t b10 = *(const uint32_t*)(h_s + (r + 8) * HPAD + kg);
                        uint32_t b11 = *(const uint32_t*)(h_s + (r + 8) * HPAD + kg + 8);
                        mma16816(acc0, a0, a1, a2, a3, b00, b01);
                        mma16816(acc1, a0, a1, a2, a3, b10, b11);
                    }
                    __syncthreads();
                }

                {
                    const int rbase = warp * 16 + r;
                    const float bl0 = blin[rows_base + rbase];
                    const float bl1 = blin[rows_base + rbase + 8];
                    const int c0 = q4 * 2;
                    log_s[rbase * LPAD + c0]           = acc0[0] + bl0;
                    log_s[rbase * LPAD + c0 + 1]       = acc0[1] + bl0;
                    log_s[(rbase + 8) * LPAD + c0]     = acc0[2] + bl1;
                    log_s[(rbase + 8) * LPAD + c0 + 1] = acc0[3] + bl1;
                    log_s[rbase * LPAD + c0 + 8]       = acc1[0] + bl0;
                    log_s[rbase * LPAD + c0 + 9]       = acc1[1] + bl0;
                    log_s[(rbase + 8) * LPAD + c0 + 8] = acc1[2] + bl1;
                    log_s[(rbase + 8) * LPAD + c0 + 9] = acc1[3] + bl1;
                }
                __syncthreads();

#pragma unroll
                for (int i = 0; i < 8; i++) {
                    int idx = tid + i * 256;
                    int row = idx & 127, b = idx >> 7;
                    out[(size_t)b * TT * VV + (size_t)t * VV + rows_base + row] =
                        log_s[row * LPAD + b];
                }

                {
                    int b = 2 * warp + (lane >> 4);
                    int l = lane & 15;
                    float s = 0.f, m = -1e30f;
#pragma unroll
                    for (int rr = 0; rr < 8; rr++) {
                        float v = log_s[(l * 8 + rr) * LPAD + b];
                        s += expf(v);
                        m = fmaxf(m, v);
                    }
#pragma unroll
                    for (int off = 8; off; off >>= 1) {
                        s += __shfl_xor_sync(0xFFFFFFFFu, s, off);
                        m = fmaxf(m, __shfl_xor_sync(0xFFFFFFFFu, m, off));
                    }
                    if (l == 0) {
                        g_pexp[t][b][chunk] = s;
                        unsigned fm = ford(m);
                        unsigned old = atomicMax(&g_approx[cur][b], fm);
                        unsigned L = old > fm ? old : fm;
                        thr_s[b] = funord(L) - TAU;
                    }
                }
                __syncthreads();

#pragma unroll
                for (int i = 0; i < 8; i++) {
                    int idx = tid + i * 256;
                    int row = idx & 127, b = idx >> 7;
                    if (log_s[row * LPAD + b] >= thr_s[b]) {
                        int slot = atomicAdd(cnt_s, 1);
                        if (slot < 128) cand_s[slot] = ((rows_base + row) << 4) | b;
                    }
                }
                __syncthreads();

                int n = *cnt_s; if (n > 128) n = 128;
                for (int e = warp; e < n; e += 8) {
                    int pk = cand_s[e];
                    int rr = pk >> 4, b = pk & 15;
                    const float4* Wr = (const float4*)(Wlin + (size_t)rr * HH);
                    const float4* hr = (const float4*)(g_h[cur] + b * HH);
                    float acc = 0.f;
#pragma unroll
                    for (int qq = 0; qq < 8; qq++) {
                        float4 w = Wr[lane + qq * 32];
                        float4 h = hr[lane + qq * 32];
                        acc += w.x * h.x + w.y * h.y + w.z * h.z + w.w * h.w;
                    }
#pragma unroll
                    for (int off = 16; off; off >>= 1)
                        acc += __shfl_xor_sync(0xFFFFFFFFu, acc, off);
                    if (lane == 0) {
                        float ex = acc + blin[rr];
                        unsigned long long pkd =
                            ((unsigned long long)ford(ex) << 32) | (unsigned)(~(unsigned)rr);
                        atomicMax(&g_amax[cur][b], pkd);
                    }
                }
                __syncthreads();
            }
        }

        grid_bar();   // logits/argmax visible; smem free for next step
    }
}

// ---------------------------------------------------------------------
__global__ void k_final(float* __restrict__ out) {
    const int t = blockIdx.x >> 4;
    const int b = blockIdx.x & 15;
    __shared__ float red[256];
    float s = 0.f;
    for (int i = threadIdx.x; i < K2_BLOCKS; i += 256) s += g_pexp[t][b][i];
    red[threadIdx.x] = s;
    __syncthreads();
    for (int off = 128; off; off >>= 1) {
        if (threadIdx.x < off) red[threadIdx.x] += red[threadIdx.x + off];
        __syncthreads();
    }
    const float lse = logf(red[0]);
    float* p = out + (size_t)b * TT * VV + (size_t)t * VV;
    for (int i = threadIdx.x; i < VV / 4; i += 256) {
        float4 v = *(float4*)(p + i * 4);
        v.x -= lse; v.y -= lse; v.z -= lse; v.w -= lse;
        *(float4*)(p + i * 4) = v;
    }
}

__global__ void k_hc(float* __restrict__ out) {
    int i = blockIdx.x * blockDim.x + threadIdx.x;
    if (i < BB * HH) {
        out[(size_t)BB * TT * VV + i]           = g_h[0][i];
        out[(size_t)BB * TT * VV + BB * HH + i] = g_c[i];
    }
}

// ---------------------------------------------------------------------
extern "C" void kernel_launch(void* const* d_in, const int* in_sizes, int n_in,
                              void* d_out, int out_size) {
    const float* h0   = (const float*)d_in[1];
    const float* c0   = (const float*)d_in[2];
    const float* emb  = (const float*)d_in[3];
    const float* Wih  = (const float*)d_in[4];
    const float* Whh  = (const float*)d_in[5];
    const float* bih  = (const float*)d_in[6];
    const float* bhh  = (const float*)d_in[7];
    const float* Wlin = (const float*)d_in[8];
    const float* blin = (const float*)d_in[9];
    float* out = (float*)d_out;

    cudaFuncSetAttribute(k_decode, cudaFuncAttributeMaxDynamicSharedMemorySize, L_SMEM);

    k_init<<<(BB * HH + 255) / 256, 256>>>(h0, c0, bih, bhh);
    k_cvt<<<(int)((size_t)VV * HH / 8 / 256), 256>>>(Wlin);
    k_cvt2<<<(int)((size_t)4 * HH * KK / 8 / 256), 256>>>(Wih, Whh);
    k_decode<<<NB, NT, L_SMEM>>>(emb, Wlin, blin, out);
    k_final<<<TT * BB, 256>>>(out);
    k_hc<<<(BB * HH + 255) / 256, 256>>>(out);
}

// round 7
// speedup vs baseline: 1.2104x; 1.2104x over previous
#include <cuda_runtime.h>
#include <cuda_fp16.h>
#include <math.h>
#include <stdint.h>

#define BB 16
#define TT 128
#define HH 1024
#define EE 1024
#define VV 32000

#define K1_BLOCKS 256
#define K1_THREADS 256

// ---- K1 smem (dynamic, bytes) ----
#define XH0_OFF  0            // 16 x 256 fp32 = 16384
#define XH1_OFF  16384
#define WT0_OFF  32768        // 16 rows x 256 fp32 = 16384
#define WT1_OFF  49152
#define GATE_OFF 65536        // 16 x 16 fp32 = 1024
#define TOKS_OFF 66560        // 16 int
#define K1_SMEM  66624

// ---- K2 config ----
#define K2_ROWS   128
#define K2_BLOCKS (VV / K2_ROWS)     // 250
#define K2_THREADS 256
#define NCHUNK 16
#define TAU 0.05f
#define WPAD 72
#define HPAD 1032
#define LPAD 17

// K2 smem offsets (3-stage W pipeline)
#define H_OFF    0            // 16*1032*2 = 33024
#define W0_OFF   33024        // 128*72*2 = 18432
#define W1_OFF   51456
#define W2_OFF   69888
#define LOG_OFF  88320        // 128*17*4 = 8704
#define THR_OFF  97024
#define CNT_OFF  97088
#define CAND_OFF 97104        // 128*4
#define K2_SMEM  97616

// -------- persistent scratch --------
__device__ float  g_h[2][BB * HH];
__device__ float  g_c[BB * HH];
__device__ __half g_h16[BB * HH];
__device__ __half g_W16[(size_t)VV * HH];        // 64 MB fp16 W_lin
__device__ unsigned long long g_amax[2][BB];
__device__ unsigned g_approx[2][BB];
__device__ float  g_pexp[TT][BB][K2_BLOCKS];

// ---------------- helpers ----------------
__device__ __forceinline__ unsigned ford(float f) {
    unsigned u = __float_as_uint(f);
    return (u & 0x80000000u) ? ~u : (u | 0x80000000u);
}
__device__ __forceinline__ float funord(unsigned v) {
    unsigned bits = (v & 0x80000000u) ? (v ^ 0x80000000u) : ~v;
    return __uint_as_float(bits);
}
#define CP16(dst, src)  asm volatile("cp.async.cg.shared.global [%0], [%1], 16;" :: "r"(dst), "l"(src) : "memory")
#define CP_COMMIT()     asm volatile("cp.async.commit_group;" ::: "memory")
#define CP_WAIT2()      asm volatile("cp.async.wait_group 2;" ::: "memory")
#define CP_WAIT1()      asm volatile("cp.async.wait_group 1;" ::: "memory")
#define CP_WAIT0()      asm volatile("cp.async.wait_group 0;" ::: "memory")

__device__ __forceinline__ uint32_t smem_u32(const void* p) {
    uint32_t a;
    asm("{ .reg .u64 t; cvta.to.shared.u64 t, %1; cvt.u32.u64 %0, t; }" : "=r"(a) : "l"(p));
    return a;
}
__device__ __forceinline__ void mma16816(float* c, uint32_t a0, uint32_t a1,
                                         uint32_t a2, uint32_t a3,
                                         uint32_t b0, uint32_t b1) {
    asm volatile(
        "mma.sync.aligned.m16n8k16.row.col.f32.f16.f16.f32 "
        "{%0,%1,%2,%3}, {%4,%5,%6,%7}, {%8,%9}, {%0,%1,%2,%3};"
        : "+f"(c[0]), "+f"(c[1]), "+f"(c[2]), "+f"(c[3])
        : "r"(a0), "r"(a1), "r"(a2), "r"(a3), "r"(b0), "r"(b1));
}

// ---------------------------------------------------------------------
__global__ void k_init(const float* __restrict__ h0, const float* __restrict__ c0) {
    int i = blockIdx.x * blockDim.x + threadIdx.x;
    if (i < BB * HH) {
        g_h[0][i] = h0[i];
        g_c[i]    = c0[i];
    }
    if (i < BB) g_amax[0][i] = (unsigned long long)(~1u);   // SOS = 1
}

__global__ void k_cvt(const float* __restrict__ W) {
    size_t i = ((size_t)blockIdx.x * 256 + threadIdx.x) * 8;
    float4 a = *(const float4*)(W + i);
    float4 b = *(const float4*)(W + i + 4);
    __half2 p0 = __floats2half2_rn(a.x, a.y), p1 = __floats2half2_rn(a.z, a.w);
    __half2 p2 = __floats2half2_rn(b.x, b.y), p3 = __floats2half2_rn(b.z, b.w);
    uint4 o;
    o.x = *(uint32_t*)&p0; o.y = *(uint32_t*)&p1;
    o.z = *(uint32_t*)&p2; o.w = *(uint32_t*)&p3;
    *(uint4*)(g_W16 + i) = o;
}

// ---------------------------------------------------------------------
// K1 v4: fp32 LSTM step; BOTH xh and W tiles via cp.async double-buffer.
// 256 blocks x 256 threads; block owns 4 hidden units = 16 gate rows.
__global__ void __launch_bounds__(K1_THREADS)
k_lstm(int t,
       const float* __restrict__ emb,
       const float* __restrict__ Wih, const float* __restrict__ Whh,
       const float* __restrict__ bih, const float* __restrict__ bhh) {
    extern __shared__ char sm[];
    const uint32_t smem_base = smem_u32(sm);
    float* gate_s = (float*)(sm + GATE_OFF);
    int*   tok_s  = (int*)(sm + TOKS_OFF);

    const int tid  = threadIdx.x;
    const int pr   = t & 1;
    const int cur  = (t + 1) & 1;

    if (tid < BB) tok_s[tid] = (int)(~(unsigned)g_amax[pr][tid]);
    if (blockIdx.x == 0 && tid < BB) { g_amax[cur][tid] = 0ull; g_approx[cur][tid] = 0u; }
    __syncthreads();

    const int warp = tid >> 5, lane = tid & 31;
    const int r0i = 2 * warp, r1i = r0i + 1;

    // tile loader: 1024 float4 per tile for xh and for W (4 per thread each)
    auto issue_tile = [&](int kt, int buf) {
        const int kbase = kt * 256;
#pragma unroll
        for (int q = 0; q < 4; q++) {
            int i4 = tid + q * 256;
            // xh: row b = i4>>6, float4 col = i4&63
            int b = i4 >> 6, k16 = i4 & 63;
            int kg = kbase + k16 * 4;
            const float* xs = (kg < EE) ? (emb + (size_t)tok_s[b] * EE + kg)
                                        : (g_h[pr] + b * HH + (kg - EE));
            CP16(smem_base + (buf ? XH1_OFF : XH0_OFF) + (uint32_t)(b * 1024 + k16 * 16), xs);
            // W: local row li = i4>>6 -> global row (li&3)*HH + blockIdx*4 + (li>>2)
            int li = b;
            int grow = (li & 3) * HH + blockIdx.x * 4 + (li >> 2);
            const float* ws = (kbase < EE)
                ? (Wih + (size_t)grow * EE + kbase + k16 * 4)
                : (Whh + (size_t)grow * HH + (kbase - EE) + k16 * 4);
            CP16(smem_base + (buf ? WT1_OFF : WT0_OFF) + (uint32_t)(li * 1024 + k16 * 16), ws);
        }
        CP_COMMIT();
    };

    issue_tile(0, 0);

    float acc0[16], acc1[16];
#pragma unroll
    for (int b = 0; b < 16; b++) { acc0[b] = 0.f; acc1[b] = 0.f; }

    for (int kt = 0; kt < 8; kt++) {
        if (kt + 1 < 8) { issue_tile(kt + 1, (kt + 1) & 1); CP_WAIT1(); }
        else            { CP_WAIT0(); }
        __syncthreads();

        const float* xh = (const float*)(sm + ((kt & 1) ? XH1_OFF : XH0_OFF));
        const float* wt = (const float*)(sm + ((kt & 1) ? WT1_OFF : WT0_OFF));
#pragma unroll
        for (int it = 0; it < 2; it++) {
            int k0 = lane * 4 + it * 128;
            float4 w0 = *(const float4*)(wt + r0i * 256 + k0);
            float4 w1 = *(const float4*)(wt + r1i * 256 + k0);
#pragma unroll
            for (int b = 0; b < 16; b++) {
                float4 hv = *(const float4*)(xh + b * 256 + k0);
                acc0[b] += w0.x * hv.x + w0.y * hv.y + w0.z * hv.z + w0.w * hv.w;
                acc1[b] += w1.x * hv.x + w1.y * hv.y + w1.z * hv.z + w1.w * hv.w;
            }
        }
        __syncthreads();
    }

#pragma unroll
    for (int b = 0; b < 16; b++) {
        float v0 = acc0[b], v1 = acc1[b];
#pragma unroll
        for (int off = 16; off; off >>= 1) {
            v0 += __shfl_xor_sync(0xFFFFFFFFu, v0, off);
            v1 += __shfl_xor_sync(0xFFFFFFFFu, v1, off);
        }
        if (lane == 0) { gate_s[r0i * 16 + b] = v0; gate_s[r1i * 16 + b] = v1; }
    }
    __syncthreads();

    if (tid < 64) {
        int u = tid >> 4, b = tid & 15;
        int j = blockIdx.x * 4 + u;
        // gate_s local row li: u=li>>2, gs=li&3 -> li = u*4+gs
        float gi = gate_s[(u * 4 + 0) * 16 + b] + bih[0 * HH + j] + bhh[0 * HH + j];
        float gf = gate_s[(u * 4 + 1) * 16 + b] + bih[1 * HH + j] + bhh[1 * HH + j];
        float gg = gate_s[(u * 4 + 2) * 16 + b] + bih[2 * HH + j] + bhh[2 * HH + j];
        float go = gate_s[(u * 4 + 3) * 16 + b] + bih[3 * HH + j] + bhh[3 * HH + j];
        float si = 1.f / (1.f + expf(-gi));
        float sf = 1.f / (1.f + expf(-gf));
        float so = 1.f / (1.f + expf(-go));
        float c  = sf * g_c[b * HH + j] + si * tanhf(gg);
        g_c[b * HH + j] = c;
        float h = so * tanhf(c);
        g_h[cur][b * HH + j] = h;
        g_h16[b * HH + j] = __float2half(h);
    }
}

// ---------------------------------------------------------------------
// K2 v2: fp16 HMMA logits GEMM, 3-stage cp.async pipeline + exact fp32 rescue
__global__ void __launch_bounds__(K2_THREADS)
k_logits(int t, const float* __restrict__ Wlin, const float* __restrict__ blin,
         float* __restrict__ out) {
    extern __shared__ char sm[];
    const uint32_t smem_base = smem_u32(sm);
    __half* h_s   = (__half*)(sm + H_OFF);
    float*  log_s = (float*)(sm + LOG_OFF);
    float*  thr_s = (float*)(sm + THR_OFF);
    int*    cnt_s = (int*)(sm + CNT_OFF);
    int*    cand_s = (int*)(sm + CAND_OFF);

    const int tid = threadIdx.x, warp = tid >> 5, lane = tid & 31;
    const int cur = (t + 1) & 1;
    const int r = lane >> 2, q4 = lane & 3;

    if (tid == 0) *cnt_s = 0;

    // load h16 into padded smem
#pragma unroll
    for (int q = 0; q < 8; q++) {
        int i = tid + q * 256;
        int b = i >> 7, k8 = i & 127;
        float4 v = *(const float4*)(g_h16 + (size_t)b * HH + k8 * 8);
        *(float4*)(h_s + b * HPAD + k8 * 8) = v;
    }

    const size_t wrow_base = (size_t)blockIdx.x * K2_ROWS * HH;
    const uint32_t woff[3] = {W0_OFF, W1_OFF, W2_OFF};

    auto issue_w = [&](int c) {
        uint32_t o = woff[c % 3];
#pragma unroll
        for (int qq = 0; qq < 4; qq++) {
            int i = tid + qq * 256;
            int row = i >> 3, col16 = i & 7;
            CP16(smem_base + o + (uint32_t)(row * WPAD + col16 * 8) * 2,
                 g_W16 + wrow_base + (size_t)row * HH + c * 64 + col16 * 8);
        }
        CP_COMMIT();
    };

    issue_w(0);
    issue_w(1);

    float acc0[4] = {0.f, 0.f, 0.f, 0.f};
    float acc1[4] = {0.f, 0.f, 0.f, 0.f};

    for (int c = 0; c < NCHUNK; c++) {
        if (c + 2 < NCHUNK) { issue_w(c + 2); CP_WAIT2(); }
        else if (c + 1 < NCHUNK) { CP_WAIT1(); }
        else { CP_WAIT0(); }
        __syncthreads();

        const __half* wb = (const __half*)(sm + woff[c % 3]);
#pragma unroll
        for (int ks = 0; ks < 4; ks++) {
            int k0 = ks * 16 + q4 * 2;
            uint32_t a0 = *(const uint32_t*)(wb + (warp * 16 + r) * WPAD + k0);
            uint32_t a1 = *(const uint32_t*)(wb + (warp * 16 + r + 8) * WPAD + k0);
            uint32_t a2 = *(const uint32_t*)(wb + (warp * 16 + r) * WPAD + k0 + 8);
            uint32_t a3 = *(const uint32_t*)(wb + (warp * 16 + r + 8) * WPAD + k0 + 8);
            int kg = c * 64 + k0;
            uint32_t b00 = *(const uint32_t*)(h_s + r * HPAD + kg);
            uint32_t b01 = *(const uint32_t*)(h_s + r * HPAD + kg + 8);
            uint32_t b10 = *(const uint32_t*)(h_s + (r + 8) * HPAD + kg);
            uint32_t b11 = *(const uint32_t*)(h_s + (r + 8) * HPAD + kg + 8);
            mma16816(acc0, a0, a1, a2, a3, b00, b01);
            mma16816(acc1, a0, a1, a2, a3, b10, b11);
        }
        __syncthreads();
    }

    {
        const int rbase = warp * 16 + r;
        const float bl0 = blin[blockIdx.x * K2_ROWS + rbase];
        const float bl1 = blin[blockIdx.x * K2_ROWS + rbase + 8];
        const int c0 = q4 * 2;
        log_s[rbase * LPAD + c0]           = acc0[0] + bl0;
        log_s[rbase * LPAD + c0 + 1]       = acc0[1] + bl0;
        log_s[(rbase + 8) * LPAD + c0]     = acc0[2] + bl1;
        log_s[(rbase + 8) * LPAD + c0 + 1] = acc0[3] + bl1;
        log_s[rbase * LPAD + c0 + 8]       = acc1[0] + bl0;
        log_s[rbase * LPAD + c0 + 9]       = acc1[1] + bl0;
        log_s[(rbase + 8) * LPAD + c0 + 8] = acc1[2] + bl1;
        log_s[(rbase + 8) * LPAD + c0 + 9] = acc1[3] + bl1;
    }
    __syncthreads();

#pragma unroll
    for (int i = 0; i < 8; i++) {
        int idx = tid + i * 256;
        int row = idx & 127, b = idx >> 7;
        out[(size_t)b * TT * VV + (size_t)t * VV + blockIdx.x * K2_ROWS + row] =
            log_s[row * LPAD + b];
    }

    {
        int b = 2 * warp + (lane >> 4);
        int l = lane & 15;
        float s = 0.f, m = -1e30f;
#pragma unroll
        for (int rr = 0; rr < 8; rr++) {
            float v = log_s[(l * 8 + rr) * LPAD + b];
            s += expf(v);
            m = fmaxf(m, v);
        }
#pragma unroll
        for (int off = 8; off; off >>= 1) {
            s += __shfl_xor_sync(0xFFFFFFFFu, s, off);
            m = fmaxf(m, __shfl_xor_sync(0xFFFFFFFFu, m, off));
        }
        if (l == 0) {
            g_pexp[t][b][blockIdx.x] = s;
            unsigned fm = ford(m);
            unsigned old = atomicMax(&g_approx[cur][b], fm);
            unsigned L = old > fm ? old : fm;
            thr_s[b] = funord(L) - TAU;
        }
    }
    __syncthreads();

#pragma unroll
    for (int i = 0; i < 8; i++) {
        int idx = tid + i * 256;
        int row = idx & 127, b = idx >> 7;
        if (log_s[row * LPAD + b] >= thr_s[b]) {
            int slot = atomicAdd(cnt_s, 1);
            if (slot < 128) cand_s[slot] = ((blockIdx.x * K2_ROWS + row) << 4) | b;
        }
    }
    __syncthreads();

    int n = *cnt_s; if (n > 128) n = 128;
    for (int e = warp; e < n; e += 8) {
        int pk = cand_s[e];
        int rr = pk >> 4, b = pk & 15;
        const float4* Wr = (const float4*)(Wlin + (size_t)rr * HH);
        const float4* hr = (const float4*)(g_h[cur] + b * HH);
        float acc = 0.f;
#pragma unroll
        for (int qq = 0; qq < 8; qq++) {
            float4 w = Wr[lane + qq * 32];
            float4 h = hr[lane + qq * 32];
            acc += w.x * h.x + w.y * h.y + w.z * h.z + w.w * h.w;
        }
#pragma unroll
        for (int off = 16; off; off >>= 1) acc += __shfl_xor_sync(0xFFFFFFFFu, acc, off);
        if (lane == 0) {
            float ex = acc + blin[rr];
            unsigned long long pkd =
                ((unsigned long long)ford(ex) << 32) | (unsigned)(~(unsigned)rr);
            atomicMax(&g_amax[cur][b], pkd);
        }
    }
}

// ---------------------------------------------------------------------
__global__ void k_final(float* __restrict__ out) {
    const int t = blockIdx.x >> 4;
    const int b = blockIdx.x & 15;
    __shared__ float red[256];
    float s = 0.f;
    for (int i = threadIdx.x; i < K2_BLOCKS; i += 256) s += g_pexp[t][b][i];
    red[threadIdx.x] = s;
    __syncthreads();
    for (int off = 128; off; off >>= 1) {
        if (threadIdx.x < off) red[threadIdx.x] += red[threadIdx.x + off];
        __syncthreads();
    }
    const float lse = logf(red[0]);
    float* p = out + (size_t)b * TT * VV + (size_t)t * VV;
    for (int i = threadIdx.x; i < VV / 4; i += 256) {
        float4 v = *(float4*)(p + i * 4);
        v.x -= lse; v.y -= lse; v.z -= lse; v.w -= lse;
        *(float4*)(p + i * 4) = v;
    }
}

__global__ void k_hc(float* __restrict__ out) {
    int i = blockIdx.x * blockDim.x + threadIdx.x;
    if (i < BB * HH) {
        out[(size_t)BB * TT * VV + i]           = g_h[0][i];
        out[(size_t)BB * TT * VV + BB * HH + i] = g_c[i];
    }
}

// ---------------------------------------------------------------------
extern "C" void kernel_launch(void* const* d_in, const int* in_sizes, int n_in,
                              void* d_out, int out_size) {
    const float* h0   = (const float*)d_in[1];
    const float* c0   = (const float*)d_in[2];
    const float* emb  = (const float*)d_in[3];
    const float* Wih  = (const float*)d_in[4];
    const float* Whh  = (const float*)d_in[5];
    const float* bih  = (const float*)d_in[6];
    const float* bhh  = (const float*)d_in[7];
    const float* Wlin = (const float*)d_in[8];
    const float* blin = (const float*)d_in[9];
    float* out = (float*)d_out;

    cudaFuncSetAttribute(k_logits, cudaFuncAttributeMaxDynamicSharedMemorySize, K2_SMEM);
    cudaFuncSetAttribute(k_lstm,   cudaFuncAttributeMaxDynamicSharedMemorySize, K1_SMEM);

    k_init<<<(BB * HH + 255) / 256, 256>>>(h0, c0);
    k_cvt<<<(int)((size_t)VV * HH / 8 / 256), 256>>>(Wlin);
    for (int t = 0; t < TT; t++) {
        k_lstm<<<K1_BLOCKS, K1_THREADS, K1_SMEM>>>(t, emb, Wih, Whh, bih, bhh);
        k_logits<<<K2_BLOCKS, K2_THREADS, K2_SMEM>>>(t, Wlin, blin, out);
    }
    k_final<<<TT * BB, 256>>>(out);
    k_hc<<<(BB * HH + 255) / 256, 256>>>(out);
}

// round 8
// speedup vs baseline: 1.2205x; 1.0084x over previous
#include <cuda_runtime.h>
#include <cuda_fp16.h>
#include <math.h>
#include <stdint.h>

#define BB 16
#define TT 128
#define HH 1024
#define EE 1024
#define VV 32000
#define KK 2048

// ---- K1 (HMMA LSTM) ----
#define K1_BLOCKS 256
#define K1_THREADS 256
// smem offsets (bytes); x planes stride 264 halves = 528 B
#define XHI0_OFF 0          // 16*264*2 = 8448
#define XLO0_OFF 8448
#define XHI1_OFF 16896
#define XLO1_OFF 25344
#define WH0_OFF  33792      // 16*264*2 = 8448
#define WL0_OFF  42240
#define WH1_OFF  50688
#define WL1_OFF  59136
#define RED_OFF  67584      // 8*16*17*4 = 8704
#define TOK_OFF  76288      // 16*4
#define K1_SMEM  76352

// ---- K2 (logits) ----
#define K2_ROWS   128
#define K2_BLOCKS (VV / K2_ROWS)     // 250
#define K2_THREADS 256
#define NCHUNK 16
#define TAU 0.05f
#define WPAD 72
#define HPAD 1032
#define LPAD 17
#define H_OFF    0
#define W0_OFF   33024
#define W1_OFF   51456
#define W2_OFF   69888
#define LOG_OFF  88320
#define THR_OFF  97024
#define CNT_OFF  97088
#define CAND_OFF 97104
#define K2_SMEM  97616

// -------- persistent scratch --------
__device__ float  g_h[2][BB * HH];
__device__ float  g_c[BB * HH];
__device__ __half g_h16[BB * HH];
__device__ __half g_W16[(size_t)VV * HH];        // 64 MB fp16 W_lin
__device__ __half g_Whi[(size_t)4 * HH * KK];    // split gate weights (permuted rows)
__device__ __half g_Wlo[(size_t)4 * HH * KK];
__device__ float  g_pb[4 * HH];                  // permuted combined bias
__device__ unsigned long long g_amax[2][BB];
__device__ unsigned g_approx[2][BB];
__device__ float  g_pexp[TT][BB][K2_BLOCKS];

// ---------------- helpers ----------------
__device__ __forceinline__ unsigned ford(float f) {
    unsigned u = __float_as_uint(f);
    return (u & 0x80000000u) ? ~u : (u | 0x80000000u);
}
__device__ __forceinline__ float funord(unsigned v) {
    unsigned bits = (v & 0x80000000u) ? (v ^ 0x80000000u) : ~v;
    return __uint_as_float(bits);
}
#define CP16(dst, src)  asm volatile("cp.async.cg.shared.global [%0], [%1], 16;" :: "r"(dst), "l"(src) : "memory")
#define CP_COMMIT()     asm volatile("cp.async.commit_group;" ::: "memory")
#define CP_WAIT2()      asm volatile("cp.async.wait_group 2;" ::: "memory")
#define CP_WAIT1()      asm volatile("cp.async.wait_group 1;" ::: "memory")
#define CP_WAIT0()      asm volatile("cp.async.wait_group 0;" ::: "memory")

__device__ __forceinline__ uint32_t smem_u32(const void* p) {
    uint32_t a;
    asm("{ .reg .u64 t; cvta.to.shared.u64 t, %1; cvt.u32.u64 %0, t; }" : "=r"(a) : "l"(p));
    return a;
}
__device__ __forceinline__ void mma16816(float* c, uint32_t a0, uint32_t a1,
                                         uint32_t a2, uint32_t a3,
                                         uint32_t b0, uint32_t b1) {
    asm volatile(
        "mma.sync.aligned.m16n8k16.row.col.f32.f16.f16.f32 "
        "{%0,%1,%2,%3}, {%4,%5,%6,%7}, {%8,%9}, {%0,%1,%2,%3};"
        : "+f"(c[0]), "+f"(c[1]), "+f"(c[2]), "+f"(c[3])
        : "r"(a0), "r"(a1), "r"(a2), "r"(a3), "r"(b0), "r"(b1));
}

// ---------------------------------------------------------------------
__global__ void k_init(const float* __restrict__ h0, const float* __restrict__ c0,
                       const float* __restrict__ bih, const float* __restrict__ bhh) {
    int i = blockIdx.x * blockDim.x + threadIdx.x;
    if (i < BB * HH) {
        g_h[0][i] = h0[i];
        g_c[i]    = c0[i];
    }
    if (i < BB) g_amax[0][i] = (unsigned long long)(~1u);   // SOS = 1
    if (i < 4 * HH) {
        int j = i >> 2, g = i & 3;
        int orig = g * HH + j;
        g_pb[i] = bih[orig] + bhh[orig];
    }
}

__global__ void k_cvt(const float* __restrict__ W) {
    size_t i = ((size_t)blockIdx.x * 256 + threadIdx.x) * 8;
    float4 a = *(const float4*)(W + i);
    float4 b = *(const float4*)(W + i + 4);
    __half2 p0 = __floats2half2_rn(a.x, a.y), p1 = __floats2half2_rn(a.z, a.w);
    __half2 p2 = __floats2half2_rn(b.x, b.y), p3 = __floats2half2_rn(b.z, b.w);
    uint4 o;
    o.x = *(uint32_t*)&p0; o.y = *(uint32_t*)&p1;
    o.z = *(uint32_t*)&p2; o.w = *(uint32_t*)&p3;
    *(uint4*)(g_W16 + i) = o;
}

// gate weights -> split fp16, permuted rows (new_row = unit*4 + gate), K = [Wih | Whh]
__global__ void k_cvt2(const float* __restrict__ Wih, const float* __restrict__ Whh) {
    size_t idx = ((size_t)blockIdx.x * 256 + threadIdx.x) * 8;
    int nr = (int)(idx >> 11);
    int k  = (int)(idx & 2047);
    int j = nr >> 2, g = nr & 3;
    int orig = g * HH + j;
    const float* src = (k < HH) ? (Wih + (size_t)orig * HH + k)
                                : (Whh + (size_t)orig * HH + (k - HH));
    __half hi8[8], lo8[8];
#pragma unroll
    for (int q = 0; q < 8; q++) {
        float v = src[q];
        __half h = __float2half_rn(v);
        hi8[q] = h;
        lo8[q] = __float2half_rn(v - __half2float(h));
    }
    *(uint4*)(g_Whi + idx) = *(uint4*)hi8;
    *(uint4*)(g_Wlo + idx) = *(uint4*)lo8;
}

// ---------------------------------------------------------------------
// K1 v5: split-fp16 HMMA gate GEMM; 256 blocks x 256 threads, 16 permuted
// rows/block; W hi/lo double-buffered cp.async; x converted in-kernel per chunk;
// 8-warp K-split + smem reduce + pointwise. PDL prelude prefetches W chunk 0.
__global__ void __launch_bounds__(K1_THREADS)
k_lstm(int t, const float* __restrict__ emb) {
    extern __shared__ char sm[];
    const uint32_t smem_base = smem_u32(sm);
    int*   tok_s = (int*)(sm + TOK_OFF);
    float* red   = (float*)(sm + RED_OFF);

    const int tid = threadIdx.x, warp = tid >> 5, lane = tid & 31;
    const int r = lane >> 2, q4 = lane & 3;
    const int pr = t & 1, cur = (t + 1) & 1;

    auto issue_w = [&](int c) {
        uint32_t wh = smem_base + ((c & 1) ? WH1_OFF : WH0_OFF);
        uint32_t wl = smem_base + ((c & 1) ? WL1_OFF : WL0_OFF);
#pragma unroll
        for (int q = 0; q < 2; q++) {
            int i = tid + q * 256;
            int row = i >> 5, col16 = i & 31;
            size_t src = (size_t)(blockIdx.x * 16 + row) * KK + c * 256 + col16 * 8;
            CP16(wh + (uint32_t)(row * 528 + col16 * 16), g_Whi + src);
            CP16(wl + (uint32_t)(row * 528 + col16 * 16), g_Wlo + src);
        }
        CP_COMMIT();
    };

    // ---- PDL prelude: W chunk 0 is h/token independent ----
    issue_w(0);
    cudaGridDependencySynchronize();
    cudaTriggerProgrammaticLaunchCompletion();

    if (tid < BB) tok_s[tid] = (int)(~(unsigned)g_amax[pr][tid]);
    if (blockIdx.x == 0 && tid < BB) { g_amax[cur][tid] = 0ull; g_approx[cur][tid] = 0u; }
    __syncthreads();

    auto ldg_x = [&](int c, float4* xr) {
#pragma unroll
        for (int q = 0; q < 4; q++) {
            int i4 = tid + q * 256;
            int b = i4 >> 6, k16 = i4 & 63;
            int kg = c * 256 + k16 * 4;
            const float* p = (kg < EE) ? (emb + (size_t)tok_s[b] * EE + kg)
                                       : (g_h[pr] + b * HH + (kg - EE));
            xr[q] = *(const float4*)p;
        }
    };
    auto cvst = [&](const float4* xr, int buf) {
        char* xh = sm + (buf ? XHI1_OFF : XHI0_OFF);
        char* xl = sm + (buf ? XLO1_OFF : XLO0_OFF);
#pragma unroll
        for (int q = 0; q < 4; q++) {
            int i4 = tid + q * 256;
            int b = i4 >> 6, k16 = i4 & 63;
            float4 v = xr[q];
            __half h0 = __float2half_rn(v.x), h1 = __float2half_rn(v.y);
            __half h2 = __float2half_rn(v.z), h3 = __float2half_rn(v.w);
            __half l0 = __float2half_rn(v.x - __half2float(h0));
            __half l1 = __float2half_rn(v.y - __half2float(h1));
            __half l2 = __float2half_rn(v.z - __half2float(h2));
            __half l3 = __float2half_rn(v.w - __half2float(h3));
            __half hi4[4] = {h0, h1, h2, h3};
            __half lo4[4] = {l0, l1, l2, l3};
            *(uint2*)(xh + b * 528 + k16 * 8) = *(uint2*)hi4;
            *(uint2*)(xl + b * 528 + k16 * 8) = *(uint2*)lo4;
        }
    };

    float4 xr[4];
    ldg_x(0, xr);
    issue_w(1);
    cvst(xr, 0);
    ldg_x(1, xr);
    CP_WAIT1();
    __syncthreads();

    float acc[2][4] = {{0.f,0.f,0.f,0.f},{0.f,0.f,0.f,0.f}};
    const int kw = warp * 32;

    for (int c = 0; c < 8; c++) {
        const __half* wh = (const __half*)(sm + ((c & 1) ? WH1_OFF : WH0_OFF));
        const __half* wl = (const __half*)(sm + ((c & 1) ? WL1_OFF : WL0_OFF));
        const __half* xh = (const __half*)(sm + ((c & 1) ? XHI1_OFF : XHI0_OFF));
        const __half* xl = (const __half*)(sm + ((c & 1) ? XLO1_OFF : XLO0_OFF));
#pragma unroll
        for (int s = 0; s < 2; s++) {
            int kl = kw + s * 16 + q4 * 2;
            uint32_t ah0 = *(const uint32_t*)(wh + r * 264 + kl);
            uint32_t ah1 = *(const uint32_t*)(wh + (r + 8) * 264 + kl);
            uint32_t ah2 = *(const uint32_t*)(wh + r * 264 + kl + 8);
            uint32_t ah3 = *(const uint32_t*)(wh + (r + 8) * 264 + kl + 8);
            uint32_t al0 = *(const uint32_t*)(wl + r * 264 + kl);
            uint32_t al1 = *(const uint32_t*)(wl + (r + 8) * 264 + kl);
            uint32_t al2 = *(const uint32_t*)(wl + r * 264 + kl + 8);
            uint32_t al3 = *(const uint32_t*)(wl + (r + 8) * 264 + kl + 8);
#pragma unroll
            for (int nbi = 0; nbi < 2; nbi++) {
                const __half* bx = xh + (nbi * 8 + r) * 264;
                const __half* by = xl + (nbi * 8 + r) * 264;
                uint32_t bh0 = *(const uint32_t*)(bx + kl);
                uint32_t bh1 = *(const uint32_t*)(bx + kl + 8);
                uint32_t bl0 = *(const uint32_t*)(by + kl);
                uint32_t bl1 = *(const uint32_t*)(by + kl + 8);
                mma16816(acc[nbi], ah0, ah1, ah2, ah3, bh0, bh1);
                mma16816(acc[nbi], ah0, ah1, ah2, ah3, bl0, bl1);
                mma16816(acc[nbi], al0, al1, al2, al3, bh0, bh1);
            }
        }
        if (c + 1 < 8) {
            __syncthreads();
            if (c + 2 < 8) issue_w(c + 2);
            cvst(xr, (c + 1) & 1);
            if (c + 2 < 8) { ldg_x(c + 2, xr); CP_WAIT1(); }
            else           { CP_WAIT0(); }
            __syncthreads();
        }
    }

    // reduce 8 K-slices + pointwise
#pragma unroll
    for (int nbi = 0; nbi < 2; nbi++) {
        int col = nbi * 8 + q4 * 2;
        red[warp * 272 + r * 17 + col]           = acc[nbi][0];
        red[warp * 272 + r * 17 + col + 1]       = acc[nbi][1];
        red[warp * 272 + (r + 8) * 17 + col]     = acc[nbi][2];
        red[warp * 272 + (r + 8) * 17 + col + 1] = acc[nbi][3];
    }
    __syncthreads();
    if (tid < 64) {
        int u = tid >> 4, b = tid & 15;
        float gv[4];
#pragma unroll
        for (int g = 0; g < 4; g++) {
            int row = u * 4 + g;
            float s = g_pb[blockIdx.x * 16 + row];
#pragma unroll
            for (int w = 0; w < 8; w++) s += red[w * 272 + row * 17 + b];
            gv[g] = s;
        }
        int j = blockIdx.x * 4 + u;
        float si = 1.f / (1.f + expf(-gv[0]));
        float sf = 1.f / (1.f + expf(-gv[1]));
        float so = 1.f / (1.f + expf(-gv[3]));
        float cc = sf * g_c[b * HH + j] + si * tanhf(gv[2]);
        g_c[b * HH + j] = cc;
        float h = so * tanhf(cc);
        g_h[cur][b * HH + j] = h;
        g_h16[b * HH + j] = __float2half(h);
    }
}

// ---------------------------------------------------------------------
// K2: fp16 HMMA logits GEMM, 3-stage pipeline + exact fp32 rescue; PDL prelude.
__global__ void __launch_bounds__(K2_THREADS)
k_logits(int t, const float* __restrict__ Wlin, const float* __restrict__ blin,
         float* __restrict__ out) {
    extern __shared__ char sm[];
    const uint32_t smem_base = smem_u32(sm);
    __half* h_s   = (__half*)(sm + H_OFF);
    float*  log_s = (float*)(sm + LOG_OFF);
    float*  thr_s = (float*)(sm + THR_OFF);
    int*    cnt_s = (int*)(sm + CNT_OFF);
    int*    cand_s = (int*)(sm + CAND_OFF);

    const int tid = threadIdx.x, warp = tid >> 5, lane = tid & 31;
    const int cur = (t + 1) & 1;
    const int r = lane >> 2, q4 = lane & 3;

    const size_t wrow_base = (size_t)blockIdx.x * K2_ROWS * HH;
    const uint32_t woff[3] = {W0_OFF, W1_OFF, W2_OFF};
    auto issue_w = [&](int c) {
        uint32_t o = woff[c % 3];
#pragma unroll
        for (int qq = 0; qq < 4; qq++) {
            int i = tid + qq * 256;
            int row = i >> 3, col16 = i & 7;
            CP16(smem_base + o + (uint32_t)(row * WPAD + col16 * 8) * 2,
                 g_W16 + wrow_base + (size_t)row * HH + c * 64 + col16 * 8);
        }
        CP_COMMIT();
    };

    // ---- PDL prelude: W chunks are h-independent ----
    issue_w(0);
    issue_w(1);
    cudaGridDependencySynchronize();
    cudaTriggerProgrammaticLaunchCompletion();

    if (tid == 0) *cnt_s = 0;
#pragma unroll
    for (int q = 0; q < 8; q++) {
        int i = tid + q * 256;
        int b = i >> 7, k8 = i & 127;
        float4 v = *(const float4*)(g_h16 + (size_t)b * HH + k8 * 8);
        *(float4*)(h_s + b * HPAD + k8 * 8) = v;
    }

    float acc0[4] = {0.f, 0.f, 0.f, 0.f};
    float acc1[4] = {0.f, 0.f, 0.f, 0.f};

    for (int c = 0; c < NCHUNK; c++) {
        if (c + 2 < NCHUNK) { issue_w(c + 2); CP_WAIT2(); }
        else if (c + 1 < NCHUNK) { CP_WAIT1(); }
        else { CP_WAIT0(); }
        __syncthreads();

        const __half* wb = (const __half*)(sm + woff[c % 3]);
#pragma unroll
        for (int ks = 0; ks < 4; ks++) {
            int k0 = ks * 16 + q4 * 2;
            uint32_t a0 = *(const uint32_t*)(wb + (warp * 16 + r) * WPAD + k0);
            uint32_t a1 = *(const uint32_t*)(wb + (warp * 16 + r + 8) * WPAD + k0);
            uint32_t a2 = *(const uint32_t*)(wb + (warp * 16 + r) * WPAD + k0 + 8);
            uint32_t a3 = *(const uint32_t*)(wb + (warp * 16 + r + 8) * WPAD + k0 + 8);
            int kg = c * 64 + k0;
            uint32_t b00 = *(const uint32_t*)(h_s + r * HPAD + kg);
            uint32_t b01 = *(const uint32_t*)(h_s + r * HPAD + kg + 8);
            uint32_t b10 = *(const uint32_t*)(h_s + (r + 8) * HPAD + kg);
            uint32_t b11 = *(const uint32_t*)(h_s + (r + 8) * HPAD + kg + 8);
            mma16816(acc0, a0, a1, a2, a3, b00, b01);
            mma16816(acc1, a0, a1, a2, a3, b10, b11);
        }
        __syncthreads();
    }

    {
        const int rbase = warp * 16 + r;
        const float bl0 = blin[blockIdx.x * K2_ROWS + rbase];
        const float bl1 = blin[blockIdx.x * K2_ROWS + rbase + 8];
        const int c0 = q4 * 2;
        log_s[rbase * LPAD + c0]           = acc0[0] + bl0;
        log_s[rbase * LPAD + c0 + 1]       = acc0[1] + bl0;
        log_s[(rbase + 8) * LPAD + c0]     = acc0[2] + bl1;
        log_s[(rbase + 8) * LPAD + c0 + 1] = acc0[3] + bl1;
        log_s[rbase * LPAD + c0 + 8]       = acc1[0] + bl0;
        log_s[rbase * LPAD + c0 + 9]       = acc1[1] + bl0;
        log_s[(rbase + 8) * LPAD + c0 + 8] = acc1[2] + bl1;
        log_s[(rbase + 8) * LPAD + c0 + 9] = acc1[3] + bl1;
    }
    __syncthreads();

#pragma unroll
    for (int i = 0; i < 8; i++) {
        int idx = tid + i * 256;
        int row = idx & 127, b = idx >> 7;
        out[(size_t)b * TT * VV + (size_t)t * VV + blockIdx.x * K2_ROWS + row] =
            log_s[row * LPAD + b];
    }

    {
        int b = 2 * warp + (lane >> 4);
        int l = lane & 15;
        float s = 0.f, m = -1e30f;
#pragma unroll
        for (int rr = 0; rr < 8; rr++) {
            float v = log_s[(l * 8 + rr) * LPAD + b];
            s += expf(v);
            m = fmaxf(m, v);
        }
#pragma unroll
        for (int off = 8; off; off >>= 1) {
            s += __shfl_xor_sync(0xFFFFFFFFu, s, off);
            m = fmaxf(m, __shfl_xor_sync(0xFFFFFFFFu, m, off));
        }
        if (l == 0) {
            g_pexp[t][b][blockIdx.x] = s;
            unsigned fm = ford(m);
            unsigned old = atomicMax(&g_approx[cur][b], fm);
            unsigned L = old > fm ? old : fm;
            thr_s[b] = funord(L) - TAU;
        }
    }
    __syncthreads();

#pragma unroll
    for (int i = 0; i < 8; i++) {
        int idx = tid + i * 256;
        int row = idx & 127, b = idx >> 7;
        if (log_s[row * LPAD + b] >= thr_s[b]) {
            int slot = atomicAdd(cnt_s, 1);
            if (slot < 128) cand_s[slot] = ((blockIdx.x * K2_ROWS + row) << 4) | b;
        }
    }
    __syncthreads();

    int n = *cnt_s; if (n > 128) n = 128;
    for (int e = warp; e < n; e += 8) {
        int pk = cand_s[e];
        int rr = pk >> 4, b = pk & 15;
        const float4* Wr = (const float4*)(Wlin + (size_t)rr * HH);
        const float4* hr = (const float4*)(g_h[cur] + b * HH);
        float acc = 0.f;
#pragma unroll
        for (int qq = 0; qq < 8; qq++) {
            float4 w = Wr[lane + qq * 32];
            float4 h = hr[lane + qq * 32];
            acc += w.x * h.x + w.y * h.y + w.z * h.z + w.w * h.w;
        }
#pragma unroll
        for (int off = 16; off; off >>= 1) acc += __shfl_xor_sync(0xFFFFFFFFu, acc, off);
        if (lane == 0) {
            float ex = acc + blin[rr];
            unsigned long long pkd =
                ((unsigned long long)ford(ex) << 32) | (unsigned)(~(unsigned)rr);
            atomicMax(&g_amax[cur][b], pkd);
        }
    }
}

// ---------------------------------------------------------------------
__global__ void k_final(float* __restrict__ out) {
    const int t = blockIdx.x >> 4;
    const int b = blockIdx.x & 15;
    __shared__ float red[256];
    float s = 0.f;
    for (int i = threadIdx.x; i < K2_BLOCKS; i += 256) s += g_pexp[t][b][i];
    red[threadIdx.x] = s;
    __syncthreads();
    for (int off = 128; off; off >>= 1) {
        if (threadIdx.x < off) red[threadIdx.x] += red[threadIdx.x + off];
        __syncthreads();
    }
    const float lse = logf(red[0]);
    float* p = out + (size_t)b * TT * VV + (size_t)t * VV;
    for (int i = threadIdx.x; i < VV / 4; i += 256) {
        float4 v = *(float4*)(p + i * 4);
        v.x -= lse; v.y -= lse; v.z -= lse; v.w -= lse;
        *(float4*)(p + i * 4) = v;
    }
}

__global__ void k_hc(float* __restrict__ out) {
    int i = blockIdx.x * blockDim.x + threadIdx.x;
    if (i < BB * HH) {
        out[(size_t)BB * TT * VV + i]           = g_h[0][i];
        out[(size_t)BB * TT * VV + BB * HH + i] = g_c[i];
    }
}

// ---------------------------------------------------------------------
extern "C" void kernel_launch(void* const* d_in, const int* in_sizes, int n_in,
                              void* d_out, int out_size) {
    const float* h0   = (const float*)d_in[1];
    const float* c0   = (const float*)d_in[2];
    const float* emb  = (const float*)d_in[3];
    const float* Wih  = (const float*)d_in[4];
    const float* Whh  = (const float*)d_in[5];
    const float* bih  = (const float*)d_in[6];
    const float* bhh  = (const float*)d_in[7];
    const float* Wlin = (const float*)d_in[8];
    const float* blin = (const float*)d_in[9];
    float* out = (float*)d_out;

    cudaFuncSetAttribute(k_lstm,   cudaFuncAttributeMaxDynamicSharedMemorySize, K1_SMEM);
    cudaFuncSetAttribute(k_logits, cudaFuncAttributeMaxDynamicSharedMemorySize, K2_SMEM);

    k_init<<<(BB * HH + 255) / 256, 256>>>(h0, c0, bih, bhh);
    k_cvt<<<(int)((size_t)VV * HH / 8 / 256), 256>>>(Wlin);
    k_cvt2<<<(int)((size_t)4 * HH * KK / 8 / 256), 256>>>(Wih, Whh);

    cudaLaunchAttribute pdl[1];
    pdl[0].id = cudaLaunchAttributeProgrammaticStreamSerialization;
    pdl[0].val.programmaticStreamSerializationAllowed = 1;

    for (int t = 0; t < TT; t++) {
        if (t == 0) {
            // plain launch: prelude reads g_Whi written by k_cvt2
            k_lstm<<<K1_BLOCKS, K1_THREADS, K1_SMEM>>>(0, emb);
        } else {
            cudaLaunchConfig_t cfg = {};
            cfg.gridDim = dim3(K1_BLOCKS); cfg.blockDim = dim3(K1_THREADS);
            cfg.dynamicSmemBytes = K1_SMEM; cfg.stream = 0;
            cfg.attrs = pdl; cfg.numAttrs = 1;
            cudaLaunchKernelEx(&cfg, k_lstm, t, emb);
        }
        {
            cudaLaunchConfig_t cfg = {};
            cfg.gridDim = dim3(K2_BLOCKS); cfg.blockDim = dim3(K2_THREADS);
            cfg.dynamicSmemBytes = K2_SMEM; cfg.stream = 0;
            cfg.attrs = pdl; cfg.numAttrs = 1;
            cudaLaunchKernelEx(&cfg, k_logits, t, Wlin, blin, out);
        }
    }
    k_final<<<TT * BB, 256>>>(out);
    k_hc<<<(BB * HH + 255) / 256, 256>>>(out);
}

// round 10
// speedup vs baseline: 1.2926x; 1.0591x over previous
#include <cuda_runtime.h>
#include <cuda_fp16.h>
#include <math.h>
#include <stdint.h>

#define BB 16
#define TT 128
#define HH 1024
#define EE 1024
#define VV 32000
#define KK 2048

// ---- K1 (HMMA LSTM halves) ----
#define K1_BLOCKS 256
#define K1_THREADS 256
#define XHI0_OFF 0          // 16*264*2 = 8448
#define XLO0_OFF 8448
#define XHI1_OFF 16896
#define XLO1_OFF 25344
#define WH0_OFF  33792
#define WL0_OFF  42240
#define WH1_OFF  50688
#define WL1_OFF  59136
#define RED_OFF  67584      // 8*16*17*4 = 8704
#define TOK_OFF  76288
#define K1_SMEM  76352

// ---- K2 (logits) ----
#define K2_ROWS   128
#define K2_BLOCKS (VV / K2_ROWS)     // 250
#define K2_THREADS 256
#define NCHUNK 16
#define TAU 0.05f
#define WPAD 72
#define HPAD 1032
#define LPAD 17
#define H_OFF    0
#define W0_OFF   33024
#define W1_OFF   51456
#define W2_OFF   69888
#define LOG_OFF  88320
#define THR_OFF  97024
#define CNT_OFF  97088
#define CAND_OFF 97104
#define K2_SMEM  97616

// -------- persistent scratch --------
__device__ float  g_h[2][BB * HH];
__device__ float  g_c[BB * HH];
__device__ __half g_h16[BB * HH];
__device__ __half g_W16[(size_t)VV * HH];        // 64 MB fp16 W_lin
__device__ __half g_Whi[(size_t)4 * HH * KK];    // split gate weights (permuted rows)
__device__ __half g_Wlo[(size_t)4 * HH * KK];
__device__ float  g_gH[K1_BLOCKS * 256];         // Whh@h partial gates [blk][row16][b16]
__device__ float  g_pb[4 * HH];
__device__ unsigned long long g_amax[2][BB];
__device__ unsigned g_approx[2][BB];
__device__ float  g_pexp[TT][BB][K2_BLOCKS];

// ---------------- helpers ----------------
__device__ __forceinline__ unsigned ford(float f) {
    unsigned u = __float_as_uint(f);
    return (u & 0x80000000u) ? ~u : (u | 0x80000000u);
}
__device__ __forceinline__ float funord(unsigned v) {
    unsigned bits = (v & 0x80000000u) ? (v ^ 0x80000000u) : ~v;
    return __uint_as_float(bits);
}
#define CP16(dst, src)  asm volatile("cp.async.cg.shared.global [%0], [%1], 16;" :: "r"(dst), "l"(src) : "memory")
#define CP_COMMIT()     asm volatile("cp.async.commit_group;" ::: "memory")
#define CP_WAIT2()      asm volatile("cp.async.wait_group 2;" ::: "memory")
#define CP_WAIT1()      asm volatile("cp.async.wait_group 1;" ::: "memory")
#define CP_WAIT0()      asm volatile("cp.async.wait_group 0;" ::: "memory")

__device__ __forceinline__ uint32_t smem_u32(const void* p) {
    uint32_t a;
    asm("{ .reg .u64 t; cvta.to.shared.u64 t, %1; cvt.u32.u64 %0, t; }" : "=r"(a) : "l"(p));
    return a;
}
__device__ __forceinline__ void mma16816(float* c, uint32_t a0, uint32_t a1,
                                         uint32_t a2, uint32_t a3,
                                         uint32_t b0, uint32_t b1) {
    asm volatile(
        "mma.sync.aligned.m16n8k16.row.col.f32.f16.f16.f32 "
        "{%0,%1,%2,%3}, {%4,%5,%6,%7}, {%8,%9}, {%0,%1,%2,%3};"
        : "+f"(c[0]), "+f"(c[1]), "+f"(c[2]), "+f"(c[3])
        : "r"(a0), "r"(a1), "r"(a2), "r"(a3), "r"(b0), "r"(b1));
}

// ---------------------------------------------------------------------
__global__ void k_init(const float* __restrict__ h0, const float* __restrict__ c0,
                       const float* __restrict__ bih, const float* __restrict__ bhh) {
    int i = blockIdx.x * blockDim.x + threadIdx.x;
    if (i < BB * HH) {
        g_h[0][i] = h0[i];
        g_c[i]    = c0[i];
    }
    if (i < BB) g_amax[0][i] = (unsigned long long)(~1u);   // SOS = 1
    if (i < 4 * HH) {
        int j = i >> 2, g = i & 3;
        int orig = g * HH + j;
        g_pb[i] = bih[orig] + bhh[orig];
    }
}

__global__ void k_cvt(const float* __restrict__ W) {
    size_t i = ((size_t)blockIdx.x * 256 + threadIdx.x) * 8;
    float4 a = *(const float4*)(W + i);
    float4 b = *(const float4*)(W + i + 4);
    __half2 p0 = __floats2half2_rn(a.x, a.y), p1 = __floats2half2_rn(a.z, a.w);
    __half2 p2 = __floats2half2_rn(b.x, b.y), p3 = __floats2half2_rn(b.z, b.w);
    uint4 o;
    o.x = *(uint32_t*)&p0; o.y = *(uint32_t*)&p1;
    o.z = *(uint32_t*)&p2; o.w = *(uint32_t*)&p3;
    *(uint4*)(g_W16 + i) = o;
}

// gate weights -> split fp16, permuted rows (new_row = unit*4 + gate), K = [Wih | Whh]
__global__ void k_cvt2(const float* __restrict__ Wih, const float* __restrict__ Whh) {
    size_t idx = ((size_t)blockIdx.x * 256 + threadIdx.x) * 8;
    int nr = (int)(idx >> 11);
    int k  = (int)(idx & 2047);
    int j = nr >> 2, g = nr & 3;
    int orig = g * HH + j;
    const float* src = (k < HH) ? (Wih + (size_t)orig * HH + k)
                                : (Whh + (size_t)orig * HH + (k - HH));
    __half hi8[8], lo8[8];
#pragma unroll
    for (int q = 0; q < 8; q++) {
        float v = src[q];
        __half h = __float2half_rn(v);
        hi8[q] = h;
        lo8[q] = __float2half_rn(v - __half2float(h));
    }
    *(uint4*)(g_Whi + idx) = *(uint4*)hi8;
    *(uint4*)(g_Wlo + idx) = *(uint4*)lo8;
}

// ---------------------------------------------------------------------
// k_gemmH: partial gates = Whh_split @ h_t. PDL: preload W chunk 0, grid-sync
// (waits lstmX(t-1...) full completion), trigger EARLY, then compute. The early
// trigger lets the following k_logits launch and overlap with this GEMM.
__global__ void __launch_bounds__(K1_THREADS)
k_gemmH(int t) {
    extern __shared__ char sm[];
    const uint32_t smem_base = smem_u32(sm);
    float* red = (float*)(sm + RED_OFF);

    const int tid = threadIdx.x, warp = tid >> 5, lane = tid & 31;
    const int r = lane >> 2, q4 = lane & 3;
    const int pr = t & 1;

    auto issue_w = [&](int c) {
        uint32_t wh = smem_base + ((c & 1) ? WH1_OFF : WH0_OFF);
        uint32_t wl = smem_base + ((c & 1) ? WL1_OFF : WL0_OFF);
#pragma unroll
        for (int q = 0; q < 2; q++) {
            int i = tid + q * 256;
            int row = i >> 5, col16 = i & 31;
            size_t src = (size_t)(blockIdx.x * 16 + row) * KK + EE + c * 256 + col16 * 8;
            CP16(wh + (uint32_t)(row * 528 + col16 * 16), g_Whi + src);
            CP16(wl + (uint32_t)(row * 528 + col16 * 16), g_Wlo + src);
        }
        CP_COMMIT();
    };

    issue_w(0);                                   // h-independent prefetch
    cudaGridDependencySynchronize();              // wait lstmX(t) completion
    cudaTriggerProgrammaticLaunchCompletion();    // let k_logits launch NOW

    auto ldg_x = [&](int c, float4* xr) {
#pragma unroll
        for (int q = 0; q < 4; q++) {
            int i4 = tid + q * 256;
            int b = i4 >> 6, k16 = i4 & 63;
            xr[q] = *(const float4*)(g_h[pr] + b * HH + c * 256 + k16 * 4);
        }
    };
    auto cvst = [&](const float4* xr, int buf) {
        char* xh = sm + (buf ? XHI1_OFF : XHI0_OFF);
        char* xl = sm + (buf ? XLO1_OFF : XLO0_OFF);
#pragma unroll
        for (int q = 0; q < 4; q++) {
            int i4 = tid + q * 256;
            int b = i4 >> 6, k16 = i4 & 63;
            float4 v = xr[q];
            __half h0 = __float2half_rn(v.x), h1 = __float2half_rn(v.y);
            __half h2 = __float2half_rn(v.z), h3 = __float2half_rn(v.w);
            __half l0 = __float2half_rn(v.x - __half2float(h0));
            __half l1 = __float2half_rn(v.y - __half2float(h1));
            __half l2 = __float2half_rn(v.z - __half2float(h2));
            __half l3 = __float2half_rn(v.w - __half2float(h3));
            __half hi4[4] = {h0, h1, h2, h3};
            __half lo4[4] = {l0, l1, l2, l3};
            *(uint2*)(xh + b * 528 + k16 * 8) = *(uint2*)hi4;
            *(uint2*)(xl + b * 528 + k16 * 8) = *(uint2*)lo4;
        }
    };

    float4 xr[4];
    ldg_x(0, xr);
    issue_w(1);
    cvst(xr, 0);
    ldg_x(1, xr);
    CP_WAIT1();
    __syncthreads();

    float acc[2][4] = {{0.f,0.f,0.f,0.f},{0.f,0.f,0.f,0.f}};
    const int kw = warp * 32;

    for (int c = 0; c < 4; c++) {
        const __half* wh = (const __half*)(sm + ((c & 1) ? WH1_OFF : WH0_OFF));
        const __half* wl = (const __half*)(sm + ((c & 1) ? WL1_OFF : WL0_OFF));
        const __half* xh = (const __half*)(sm + ((c & 1) ? XHI1_OFF : XHI0_OFF));
        const __half* xl = (const __half*)(sm + ((c & 1) ? XLO1_OFF : XLO0_OFF));
#pragma unroll
        for (int s = 0; s < 2; s++) {
            int kl = kw + s * 16 + q4 * 2;
            uint32_t ah0 = *(const uint32_t*)(wh + r * 264 + kl);
            uint32_t ah1 = *(const uint32_t*)(wh + (r + 8) * 264 + kl);
            uint32_t ah2 = *(const uint32_t*)(wh + r * 264 + kl + 8);
            uint32_t ah3 = *(const uint32_t*)(wh + (r + 8) * 264 + kl + 8);
            uint32_t al0 = *(const uint32_t*)(wl + r * 264 + kl);
            uint32_t al1 = *(const uint32_t*)(wl + (r + 8) * 264 + kl);
            uint32_t al2 = *(const uint32_t*)(wl + r * 264 + kl + 8);
            uint32_t al3 = *(const uint32_t*)(wl + (r + 8) * 264 + kl + 8);
#pragma unroll
            for (int nbi = 0; nbi < 2; nbi++) {
                const __half* bx = xh + (nbi * 8 + r) * 264;
                const __half* by = xl + (nbi * 8 + r) * 264;
                uint32_t bh0 = *(const uint32_t*)(bx + kl);
                uint32_t bh1 = *(const uint32_t*)(bx + kl + 8);
                uint32_t bl0 = *(const uint32_t*)(by + kl);
                uint32_t bl1 = *(const uint32_t*)(by + kl + 8);
                mma16816(acc[nbi], ah0, ah1, ah2, ah3, bh0, bh1);
                mma16816(acc[nbi], ah0, ah1, ah2, ah3, bl0, bl1);
                mma16816(acc[nbi], al0, al1, al2, al3, bh0, bh1);
            }
        }
        if (c + 1 < 4) {
            __syncthreads();
            if (c + 2 < 4) issue_w(c + 2);
            cvst(xr, (c + 1) & 1);
            if (c + 2 < 4) { ldg_x(c + 2, xr); CP_WAIT1(); }
            else           { CP_WAIT0(); }
            __syncthreads();
        }
    }

#pragma unroll
    for (int nbi = 0; nbi < 2; nbi++) {
        int col = nbi * 8 + q4 * 2;
        red[warp * 272 + r * 17 + col]           = acc[nbi][0];
        red[warp * 272 + r * 17 + col + 1]       = acc[nbi][1];
        red[warp * 272 + (r + 8) * 17 + col]     = acc[nbi][2];
        red[warp * 272 + (r + 8) * 17 + col + 1] = acc[nbi][3];
    }
    __syncthreads();
    if (tid < 64) {
        int u = tid >> 4, b = tid & 15;
#pragma unroll
        for (int g = 0; g < 4; g++) {
            int row = u * 4 + g;
            float s = 0.f;
#pragma unroll
            for (int w = 0; w < 8; w++) s += red[w * 272 + row * 17 + b];
            g_gH[blockIdx.x * 256 + row * 16 + b] = s;
        }
    }
}

// ---------------------------------------------------------------------
// k_lstmX: gates = Wih_split @ emb[tok] + g_gH + bias; pointwise. PLAIN launch
// (full stream serialization -> sees completed g_gH and g_amax).
__global__ void __launch_bounds__(K1_THREADS)
k_lstmX(int t, const float* __restrict__ emb) {
    extern __shared__ char sm[];
    const uint32_t smem_base = smem_u32(sm);
    int*   tok_s = (int*)(sm + TOK_OFF);
    float* red   = (float*)(sm + RED_OFF);

    const int tid = threadIdx.x, warp = tid >> 5, lane = tid & 31;
    const int r = lane >> 2, q4 = lane & 3;
    const int pr = t & 1, cur = (t + 1) & 1;

    auto issue_w = [&](int c) {
        uint32_t wh = smem_base + ((c & 1) ? WH1_OFF : WH0_OFF);
        uint32_t wl = smem_base + ((c & 1) ? WL1_OFF : WL0_OFF);
#pragma unroll
        for (int q = 0; q < 2; q++) {
            int i = tid + q * 256;
            int row = i >> 5, col16 = i & 31;
            size_t src = (size_t)(blockIdx.x * 16 + row) * KK + c * 256 + col16 * 8;
            CP16(wh + (uint32_t)(row * 528 + col16 * 16), g_Whi + src);
            CP16(wl + (uint32_t)(row * 528 + col16 * 16), g_Wlo + src);
        }
        CP_COMMIT();
    };

    issue_w(0);

    if (tid < BB) tok_s[tid] = (int)(~(unsigned)g_amax[pr][tid]);
    if (blockIdx.x == 0 && tid < BB) { g_amax[cur][tid] = 0ull; g_approx[cur][tid] = 0u; }
    __syncthreads();

    auto ldg_x = [&](int c, float4* xr) {
#pragma unroll
        for (int q = 0; q < 4; q++) {
            int i4 = tid + q * 256;
            int b = i4 >> 6, k16 = i4 & 63;
            xr[q] = *(const float4*)(emb + (size_t)tok_s[b] * EE + c * 256 + k16 * 4);
        }
    };
    auto cvst = [&](const float4* xr, int buf) {
        char* xh = sm + (buf ? XHI1_OFF : XHI0_OFF);
        char* xl = sm + (buf ? XLO1_OFF : XLO0_OFF);
#pragma unroll
        for (int q = 0; q < 4; q++) {
            int i4 = tid + q * 256;
            int b = i4 >> 6, k16 = i4 & 63;
            float4 v = xr[q];
            __half h0 = __float2half_rn(v.x), h1 = __float2half_rn(v.y);
            __half h2 = __float2half_rn(v.z), h3 = __float2half_rn(v.w);
            __half l0 = __float2half_rn(v.x - __half2float(h0));
            __half l1 = __float2half_rn(v.y - __half2float(h1));
            __half l2 = __float2half_rn(v.z - __half2float(h2));
            __half l3 = __float2half_rn(v.w - __half2float(h3));
            __half hi4[4] = {h0, h1, h2, h3};
            __half lo4[4] = {l0, l1, l2, l3};
            *(uint2*)(xh + b * 528 + k16 * 8) = *(uint2*)hi4;
            *(uint2*)(xl + b * 528 + k16 * 8) = *(uint2*)lo4;
        }
    };

    float4 xr[4];
    ldg_x(0, xr);
    issue_w(1);
    cvst(xr, 0);
    ldg_x(1, xr);
    CP_WAIT1();
    __syncthreads();

    float acc[2][4] = {{0.f,0.f,0.f,0.f},{0.f,0.f,0.f,0.f}};
    const int kw = warp * 32;

    for (int c = 0; c < 4; c++) {
        const __half* wh = (const __half*)(sm + ((c & 1) ? WH1_OFF : WH0_OFF));
        const __half* wl = (const __half*)(sm + ((c & 1) ? WL1_OFF : WL0_OFF));
        const __half* xh = (const __half*)(sm + ((c & 1) ? XHI1_OFF : XHI0_OFF));
        const __half* xl = (const __half*)(sm + ((c & 1) ? XLO1_OFF : XLO0_OFF));
#pragma unroll
        for (int s = 0; s < 2; s++) {
            int kl = kw + s * 16 + q4 * 2;
            uint32_t ah0 = *(const uint32_t*)(wh + r * 264 + kl);
            uint32_t ah1 = *(const uint32_t*)(wh + (r + 8) * 264 + kl);
            uint32_t ah2 = *(const uint32_t*)(wh + r * 264 + kl + 8);
            uint32_t ah3 = *(const uint32_t*)(wh + (r + 8) * 264 + kl + 8);
            uint32_t al0 = *(const uint32_t*)(wl + r * 264 + kl);
            uint32_t al1 = *(const uint32_t*)(wl + (r + 8) * 264 + kl);
            uint32_t al2 = *(const uint32_t*)(wl + r * 264 + kl + 8);
            uint32_t al3 = *(const uint32_t*)(wl + (r + 8) * 264 + kl + 8);
#pragma unroll
            for (int nbi = 0; nbi < 2; nbi++) {
                const __half* bx = xh + (nbi * 8 + r) * 264;
                const __half* by = xl + (nbi * 8 + r) * 264;
                uint32_t bh0 = *(const uint32_t*)(bx + kl);
                uint32_t bh1 = *(const uint32_t*)(bx + kl + 8);
                uint32_t bl0 = *(const uint32_t*)(by + kl);
                uint32_t bl1 = *(const uint32_t*)(by + kl + 8);
                mma16816(acc[nbi], ah0, ah1, ah2, ah3, bh0, bh1);
                mma16816(acc[nbi], ah0, ah1, ah2, ah3, bl0, bl1);
                mma16816(acc[nbi], al0, al1, al2, al3, bh0, bh1);
            }
        }
        if (c + 1 < 4) {
            __syncthreads();
            if (c + 2 < 4) issue_w(c + 2);
            cvst(xr, (c + 1) & 1);
            if (c + 2 < 4) { ldg_x(c + 2, xr); CP_WAIT1(); }
            else           { CP_WAIT0(); }
            __syncthreads();
        }
    }

#pragma unroll
    for (int nbi = 0; nbi < 2; nbi++) {
        int col = nbi * 8 + q4 * 2;
        red[warp * 272 + r * 17 + col]           = acc[nbi][0];
        red[warp * 272 + r * 17 + col + 1]       = acc[nbi][1];
        red[warp * 272 + (r + 8) * 17 + col]     = acc[nbi][2];
        red[warp * 272 + (r + 8) * 17 + col + 1] = acc[nbi][3];
    }
    __syncthreads();
    if (tid < 64) {
        int u = tid >> 4, b = tid & 15;
        float gv[4];
#pragma unroll
        for (int g = 0; g < 4; g++) {
            int row = u * 4 + g;
            float s = g_pb[blockIdx.x * 16 + row] + g_gH[blockIdx.x * 256 + row * 16 + b];
#pragma unroll
            for (int w = 0; w < 8; w++) s += red[w * 272 + row * 17 + b];
            gv[g] = s;
        }
        int j = blockIdx.x * 4 + u;
        float si = 1.f / (1.f + expf(-gv[0]));
        float sf = 1.f / (1.f + expf(-gv[1]));
        float so = 1.f / (1.f + expf(-gv[3]));
        float cc = sf * g_c[b * HH + j] + si * tanhf(gv[2]);
        g_c[b * HH + j] = cc;
        float h = so * tanhf(cc);
        g_h[cur][b * HH + j] = h;
        g_h16[b * HH + j] = __float2half(h);
    }
}

// ---------------------------------------------------------------------
// K2: fp16 HMMA logits GEMM, 3-stage pipeline + exact fp32 rescue; PDL prelude.
// Grid-sync passes as soon as the preceding k_gemmH triggers (early), so this
// body overlaps with gemmH's compute. All data it reads was finalized by lstmX.
__global__ void __launch_bounds__(K2_THREADS)
k_logits(int t, const float* __restrict__ Wlin, const float* __restrict__ blin,
         float* __restrict__ out) {
    extern __shared__ char sm[];
    const uint32_t smem_base = smem_u32(sm);
    __half* h_s   = (__half*)(sm + H_OFF);
    float*  log_s = (float*)(sm + LOG_OFF);
    float*  thr_s = (float*)(sm + THR_OFF);
    int*    cnt_s = (int*)(sm + CNT_OFF);
    int*    cand_s = (int*)(sm + CAND_OFF);

    const int tid = threadIdx.x, warp = tid >> 5, lane = tid & 31;
    const int cur = (t + 1) & 1;
    const int r = lane >> 2, q4 = lane & 3;

    const size_t wrow_base = (size_t)blockIdx.x * K2_ROWS * HH;
    const uint32_t woff[3] = {W0_OFF, W1_OFF, W2_OFF};
    auto issue_w = [&](int c) {
        uint32_t o = woff[c % 3];
#pragma unroll
        for (int qq = 0; qq < 4; qq++) {
            int i = tid + qq * 256;
            int row = i >> 3, col16 = i & 7;
            CP16(smem_base + o + (uint32_t)(row * WPAD + col16 * 8) * 2,
                 g_W16 + wrow_base + (size_t)row * HH + c * 64 + col16 * 8);
        }
        CP_COMMIT();
    };

    // ---- PDL prelude: W chunks are h-independent ----
    issue_w(0);
    issue_w(1);
    cudaGridDependencySynchronize();
    cudaTriggerProgrammaticLaunchCompletion();

    if (tid == 0) *cnt_s = 0;
#pragma unroll
    for (int q = 0; q < 8; q++) {
        int i = tid + q * 256;
        int b = i >> 7, k8 = i & 127;
        float4 v = *(const float4*)(g_h16 + (size_t)b * HH + k8 * 8);
        *(float4*)(h_s + b * HPAD + k8 * 8) = v;
    }

    float acc0[4] = {0.f, 0.f, 0.f, 0.f};
    float acc1[4] = {0.f, 0.f, 0.f, 0.f};

    for (int c = 0; c < NCHUNK; c++) {
        if (c + 2 < NCHUNK) { issue_w(c + 2); CP_WAIT2(); }
        else if (c + 1 < NCHUNK) { CP_WAIT1(); }
        else { CP_WAIT0(); }
        __syncthreads();

        const __half* wb = (const __half*)(sm + woff[c % 3]);
#pragma unroll
        for (int ks = 0; ks < 4; ks++) {
            int k0 = ks * 16 + q4 * 2;
            uint32_t a0 = *(const uint32_t*)(wb + (warp * 16 + r) * WPAD + k0);
            uint32_t a1 = *(const uint32_t*)(wb + (warp * 16 + r + 8) * WPAD + k0);
            uint32_t a2 = *(const uint32_t*)(wb + (warp * 16 + r) * WPAD + k0 + 8);
            uint32_t a3 = *(const uint32_t*)(wb + (warp * 16 + r + 8) * WPAD + k0 + 8);
            int kg = c * 64 + k0;
            uint32_t b00 = *(const uint32_t*)(h_s + r * HPAD + kg);
            uint32_t b01 = *(const uint32_t*)(h_s + r * HPAD + kg + 8);
            uint32_t b10 = *(const uint32_t*)(h_s + (r + 8) * HPAD + kg);
            uint32_t b11 = *(const uint32_t*)(h_s + (r + 8) * HPAD + kg + 8);
            mma16816(acc0, a0, a1, a2, a3, b00, b01);
            mma16816(acc1, a0, a1, a2, a3, b10, b11);
        }
        __syncthreads();
    }

    {
        const int rbase = warp * 16 + r;
        const float bl0 = blin[blockIdx.x * K2_ROWS + rbase];
        const float bl1 = blin[blockIdx.x * K2_ROWS + rbase + 8];
        const int c0 = q4 * 2;
        log_s[rbase * LPAD + c0]           = acc0[0] + bl0;
        log_s[rbase * LPAD + c0 + 1]       = acc0[1] + bl0;
        log_s[(rbase + 8) * LPAD + c0]     = acc0[2] + bl1;
        log_s[(rbase + 8) * LPAD + c0 + 1] = acc0[3] + bl1;
        log_s[rbase * LPAD + c0 + 8]       = acc1[0] + bl0;
        log_s[rbase * LPAD + c0 + 9]       = acc1[1] + bl0;
        log_s[(rbase + 8) * LPAD + c0 + 8] = acc1[2] + bl1;
        log_s[(rbase + 8) * LPAD + c0 + 9] = acc1[3] + bl1;
    }
    __syncthreads();

#pragma unroll
    for (int i = 0; i < 8; i++) {
        int idx = tid + i * 256;
        int row = idx & 127, b = idx >> 7;
        out[(size_t)b * TT * VV + (size_t)t * VV + blockIdx.x * K2_ROWS + row] =
            log_s[row * LPAD + b];
    }

    {
        int b = 2 * warp + (lane >> 4);
        int l = lane & 15;
        float s = 0.f, m = -1e30f;
#pragma unroll
        for (int rr = 0; rr < 8; rr++) {
            float v = log_s[(l * 8 + rr) * LPAD + b];
            s += expf(v);
            m = fmaxf(m, v);
        }
#pragma unroll
        for (int off = 8; off; off >>= 1) {
            s += __shfl_xor_sync(0xFFFFFFFFu, s, off);
            m = fmaxf(m, __shfl_xor_sync(0xFFFFFFFFu, m, off));
        }
        if (l == 0) {
            g_pexp[t][b][blockIdx.x] = s;
            unsigned fm = ford(m);
            unsigned old = atomicMax(&g_approx[cur][b], fm);
            unsigned L = old > fm ? old : fm;
            thr_s[b] = funord(L) - TAU;
        }
    }
    __syncthreads();

#pragma unroll
    for (int i = 0; i < 8; i++) {
        int idx = tid + i * 256;
        int row = idx & 127, b = idx >> 7;
        if (log_s[row * LPAD + b] >= thr_s[b]) {
            int slot = atomicAdd(cnt_s, 1);
            if (slot < 128) cand_s[slot] = ((blockIdx.x * K2_ROWS + row) << 4) | b;
        }
    }
    __syncthreads();

    int n = *cnt_s; if (n > 128) n = 128;
    for (int e = warp; e < n; e += 8) {
        int pk = cand_s[e];
        int rr = pk >> 4, b = pk & 15;
        const float4* Wr = (const float4*)(Wlin + (size_t)rr * HH);
        const float4* hr = (const float4*)(g_h[cur] + b * HH);
        float acc = 0.f;
#pragma unroll
        for (int qq = 0; qq < 8; qq++) {
            float4 w = Wr[lane + qq * 32];
            float4 h = hr[lane + qq * 32];
            acc += w.x * h.x + w.y * h.y + w.z * h.z + w.w * h.w;
        }
#pragma unroll
        for (int off = 16; off; off >>= 1) acc += __shfl_xor_sync(0xFFFFFFFFu, acc, off);
        if (lane == 0) {
            float ex = acc + blin[rr];
            unsigned long long pkd =
                ((unsigned long long)ford(ex) << 32) | (unsigned)(~(unsigned)rr);
            atomicMax(&g_amax[cur][b], pkd);
        }
    }
}

// ---------------------------------------------------------------------
__global__ void k_final(float* __restrict__ out) {
    const int t = blockIdx.x >> 4;
    const int b = blockIdx.x & 15;
    __shared__ float red[256];
    float s = 0.f;
    for (int i = threadIdx.x; i < K2_BLOCKS; i += 256) s += g_pexp[t][b][i];
    red[threadIdx.x] = s;
    __syncthreads();
    for (int off = 128; off; off >>= 1) {
        if (threadIdx.x < off) red[threadIdx.x] += red[threadIdx.x + off];
        __syncthreads();
    }
    const float lse = logf(red[0]);
    float* p = out + (size_t)b * TT * VV + (size_t)t * VV;
    for (int i = threadIdx.x; i < VV / 4; i += 256) {
        float4 v = *(float4*)(p + i * 4);
        v.x -= lse; v.y -= lse; v.z -= lse; v.w -= lse;
        *(float4*)(p + i * 4) = v;
    }
}

__global__ void k_hc(float* __restrict__ out) {
    int i = blockIdx.x * blockDim.x + threadIdx.x;
    if (i < BB * HH) {
        out[(size_t)BB * TT * VV + i]           = g_h[0][i];
        out[(size_t)BB * TT * VV + BB * HH + i] = g_c[i];
    }
}

// ---------------------------------------------------------------------
extern "C" void kernel_launch(void* const* d_in, const int* in_sizes, int n_in,
                              void* d_out, int out_size) {
    const float* h0   = (const float*)d_in[1];
    const float* c0   = (const float*)d_in[2];
    const float* emb  = (const float*)d_in[3];
    const float* Wih  = (const float*)d_in[4];
    const float* Whh  = (const float*)d_in[5];
    const float* bih  = (const float*)d_in[6];
    const float* bhh  = (const float*)d_in[7];
    const float* Wlin = (const float*)d_in[8];
    const float* blin = (const float*)d_in[9];
    float* out = (float*)d_out;

    cudaFuncSetAttribute(k_lstmX,  cudaFuncAttributeMaxDynamicSharedMemorySize, K1_SMEM);
    cudaFuncSetAttribute(k_gemmH,  cudaFuncAttributeMaxDynamicSharedMemorySize, K1_SMEM);
    cudaFuncSetAttribute(k_logits, cudaFuncAttributeMaxDynamicSharedMemorySize, K2_SMEM);

    cudaLaunchAttribute pdl[1];
    pdl[0].id = cudaLaunchAttributeProgrammaticStreamSerialization;
    pdl[0].val.programmaticStreamSerializationAllowed = 1;

    k_init<<<(BB * HH + 255) / 256, 256>>>(h0, c0, bih, bhh);
    k_cvt<<<(int)((size_t)VV * HH / 8 / 256), 256>>>(Wlin);
    k_cvt2<<<(int)((size_t)4 * HH * KK / 8 / 256), 256>>>(Wih, Whh);

    // gemmH(0): plain launch (needs g_h[0] from k_init, g_Whi from k_cvt2)
    k_gemmH<<<K1_BLOCKS, K1_THREADS, K1_SMEM>>>(0);

    for (int t = 0; t < TT; t++) {
        // PLAIN: full serialization -> g_gH(t) and g_amax(t) complete
        k_lstmX<<<K1_BLOCKS, K1_THREADS, K1_SMEM>>>(t, emb);

        if (t < TT - 1) {
            // PDL: prelude overlaps lstmX tail; triggers early so logits overlaps
            cudaLaunchConfig_t cfg = {};
            cfg.gridDim = dim3(K1_BLOCKS); cfg.blockDim = dim3(K1_THREADS);
            cfg.dynamicSmemBytes = K1_SMEM; cfg.stream = 0;
            cfg.attrs = pdl; cfg.numAttrs = 1;
            cudaLaunchKernelEx(&cfg, k_gemmH, t + 1);
        }
        {
            // PDL: launches as soon as gemmH triggers -> overlaps gemmH compute
            cudaLaunchConfig_t cfg = {};
            cfg.gridDim = dim3(K2_BLOCKS); cfg.blockDim = dim3(K2_THREADS);
            cfg.dynamicSmemBytes = K2_SMEM; cfg.stream = 0;
            cfg.attrs = pdl; cfg.numAttrs = 1;
            cudaLaunchKernelEx(&cfg, k_logits, t, Wlin, blin, out);
        }
    }
    k_final<<<TT * BB, 256>>>(out);
    k_hc<<<(BB * HH + 255) / 256, 256>>>(out);
}

// round 13
// speedup vs baseline: 1.5768x; 1.2199x over previous
#include <cuda_runtime.h>
#include <cuda_fp16.h>
#include <math.h>
#include <stdint.h>

#define BB 16
#define TT 128
#define HH 1024
#define EE 1024
#define VV 32000
#define KK 2048

// ---- K1 (HMMA LSTM halves) ----
#define K1_BLOCKS 256
#define K1_THREADS 256
#define XHI0_OFF 0          // 16*264*2 = 8448
#define XLO0_OFF 8448
#define XHI1_OFF 16896
#define XLO1_OFF 25344
#define WH0_OFF  33792
#define WL0_OFF  42240
#define WH1_OFF  50688
#define WL1_OFF  59136
#define RED_OFF  67584      // 8*16*17*4 = 8704
#define TOK_OFF  76288
#define K1_SMEM  76352

// ---- K2 (logits) ----
#define K2_ROWS   128
#define K2_BLOCKS (VV / K2_ROWS)     // 250
#define K2_THREADS 256
#define NCHUNK 16
#define TAU 0.05f
#define HPAD 1032
#define LPAD 17
#define H_OFF    0                   // 16*1032*2 = 33024
#define LOG_OFF  33024               // 128*17*4 = 8704
#define THR_OFF  41728
#define CNT_OFF  41792
#define CAND_OFF 41808               // 128*4
#define K2_SMEM  42320

// -------- persistent scratch --------
__device__ float  g_h[2][BB * HH];
__device__ float  g_c[BB * HH];
__device__ __half g_h16[BB * HH];
__device__ __align__(128) __half g_WF[(size_t)VV * HH];   // fragment-packed fp16 W_lin
__device__ __half g_Whi[(size_t)4 * HH * KK];
__device__ __half g_Wlo[(size_t)4 * HH * KK];
__device__ float  g_gH[K1_BLOCKS * 256];
__device__ float  g_pb[4 * HH];
__device__ unsigned long long g_amax[2][BB];
__device__ unsigned g_approx[2][BB];
__device__ float  g_pexp[TT][BB][K2_BLOCKS];

// ---------------- helpers ----------------
__device__ __forceinline__ unsigned ford(float f) {
    unsigned u = __float_as_uint(f);
    return (u & 0x80000000u) ? ~u : (u | 0x80000000u);
}
__device__ __forceinline__ float funord(unsigned v) {
    unsigned bits = (v & 0x80000000u) ? (v ^ 0x80000000u) : ~v;
    return __uint_as_float(bits);
}
#define CP16(dst, src)  asm volatile("cp.async.cg.shared.global [%0], [%1], 16;" :: "r"(dst), "l"(src) : "memory")
#define CP_COMMIT()     asm volatile("cp.async.commit_group;" ::: "memory")
#define CP_WAIT1()      asm volatile("cp.async.wait_group 1;" ::: "memory")
#define CP_WAIT0()      asm volatile("cp.async.wait_group 0;" ::: "memory")

__device__ __forceinline__ uint32_t smem_u32(const void* p) {
    uint32_t a;
    asm("{ .reg .u64 t; cvta.to.shared.u64 t, %1; cvt.u32.u64 %0, t; }" : "=r"(a) : "l"(p));
    return a;
}
__device__ __forceinline__ void mma16816(float* c, uint32_t a0, uint32_t a1,
                                         uint32_t a2, uint32_t a3,
                                         uint32_t b0, uint32_t b1) {
    asm volatile(
        "mma.sync.aligned.m16n8k16.row.col.f32.f16.f16.f32 "
        "{%0,%1,%2,%3}, {%4,%5,%6,%7}, {%8,%9}, {%0,%1,%2,%3};"
        : "+f"(c[0]), "+f"(c[1]), "+f"(c[2]), "+f"(c[3])
        : "r"(a0), "r"(a1), "r"(a2), "r"(a3), "r"(b0), "r"(b1));
}

// ---------------------------------------------------------------------
__global__ void k_init(const float* __restrict__ h0, const float* __restrict__ c0,
                       const float* __restrict__ bih, const float* __restrict__ bhh) {
    int i = blockIdx.x * blockDim.x + threadIdx.x;
    if (i < BB * HH) {
        g_h[0][i] = h0[i];
        g_c[i]    = c0[i];
    }
    if (i < BB) g_amax[0][i] = (unsigned long long)(~1u);   // SOS = 1
    if (i < 4 * HH) {
        int j = i >> 2, g = i & 3;
        int orig = g * HH + j;
        g_pb[i] = bih[orig] + bhh[orig];
    }
}

// W_lin fp32 -> fragment-packed fp16: one 16-B unit per (blk, chunk, ks, tid)
// unit = { (row0,k..k+1), (row0+8,k..k+1), (row0,k+8..k+9), (row0+8,k+8..k+9) }
// row0 = blk*128 + warp*16 + r, k = chunk*64 + ks*16 + q4*2
__global__ void k_cvtF(const float* __restrict__ W) {
    unsigned u = blockIdx.x * 256 + threadIdx.x;   // < 250*16*4*256 = 4,096,000
    int blk = u >> 14;
    int rem = u & 16383;
    int c   = rem >> 10;
    int rem2 = rem & 1023;
    int ks  = rem2 >> 8;
    int tt  = rem2 & 255;
    int warp = tt >> 5, lane = tt & 31;
    int r = lane >> 2, q4 = lane & 3;
    int row0 = blk * 128 + warp * 16 + r;
    int k = c * 64 + ks * 16 + q4 * 2;
    const float* p0 = W + (size_t)row0 * HH + k;
    const float* p1 = W + (size_t)(row0 + 8) * HH + k;
    float2 xa = *(const float2*)p0;
    float2 xb = *(const float2*)p1;
    float2 xc = *(const float2*)(p0 + 8);
    float2 xd = *(const float2*)(p1 + 8);
    __half2 ha = __floats2half2_rn(xa.x, xa.y);
    __half2 hb = __floats2half2_rn(xb.x, xb.y);
    __half2 hc = __floats2half2_rn(xc.x, xc.y);
    __half2 hd = __floats2half2_rn(xd.x, xd.y);
    uint4 o;
    o.x = *(uint32_t*)&ha; o.y = *(uint32_t*)&hb;
    o.z = *(uint32_t*)&hc; o.w = *(uint32_t*)&hd;
    *(uint4*)((char*)g_WF + (size_t)u * 16) = o;
}

// gate weights -> split fp16, permuted rows (new_row = unit*4 + gate), K = [Wih | Whh]
__global__ void k_cvt2(const float* __restrict__ Wih, const float* __restrict__ Whh) {
    size_t idx = ((size_t)blockIdx.x * 256 + threadIdx.x) * 8;
    int nr = (int)(idx >> 11);
    int k  = (int)(idx & 2047);
    int j = nr >> 2, g = nr & 3;
    int orig = g * HH + j;
    const float* src = (k < HH) ? (Wih + (size_t)orig * HH + k)
                                : (Whh + (size_t)orig * HH + (k - HH));
    __half hi8[8], lo8[8];
#pragma unroll
    for (int q = 0; q < 8; q++) {
        float v = src[q];
        __half h = __float2half_rn(v);
        hi8[q] = h;
        lo8[q] = __float2half_rn(v - __half2float(h));
    }
    *(uint4*)(g_Whi + idx) = *(uint4*)hi8;
    *(uint4*)(g_Wlo + idx) = *(uint4*)lo8;
}

// ---------------------------------------------------------------------
// k_gemmH: partial gates = Whh_split @ h_t. PDL, triggers early (R10, proven).
__global__ void __launch_bounds__(K1_THREADS)
k_gemmH(int t) {
    extern __shared__ char sm[];
    const uint32_t smem_base = smem_u32(sm);
    float* red = (float*)(sm + RED_OFF);

    const int tid = threadIdx.x, warp = tid >> 5, lane = tid & 31;
    const int r = lane >> 2, q4 = lane & 3;
    const int pr = t & 1;

    auto issue_w = [&](int c) {
        uint32_t wh = smem_base + ((c & 1) ? WH1_OFF : WH0_OFF);
        uint32_t wl = smem_base + ((c & 1) ? WL1_OFF : WL0_OFF);
#pragma unroll
        for (int q = 0; q < 2; q++) {
            int i = tid + q * 256;
            int row = i >> 5, col16 = i & 31;
            size_t src = (size_t)(blockIdx.x * 16 + row) * KK + EE + c * 256 + col16 * 8;
            CP16(wh + (uint32_t)(row * 528 + col16 * 16), g_Whi + src);
            CP16(wl + (uint32_t)(row * 528 + col16 * 16), g_Wlo + src);
        }
        CP_COMMIT();
    };

    issue_w(0);
    cudaGridDependencySynchronize();
    cudaTriggerProgrammaticLaunchCompletion();

    auto ldg_x = [&](int c, float4* xr) {
#pragma unroll
        for (int q = 0; q < 4; q++) {
            int i4 = tid + q * 256;
            int b = i4 >> 6, k16 = i4 & 63;
            xr[q] = *(const float4*)(g_h[pr] + b * HH + c * 256 + k16 * 4);
        }
    };
    auto cvst = [&](const float4* xr, int buf) {
        char* xh = sm + (buf ? XHI1_OFF : XHI0_OFF);
        char* xl = sm + (buf ? XLO1_OFF : XLO0_OFF);
#pragma unroll
        for (int q = 0; q < 4; q++) {
            int i4 = tid + q * 256;
            int b = i4 >> 6, k16 = i4 & 63;
            float4 v = xr[q];
            __half h0 = __float2half_rn(v.x), h1 = __float2half_rn(v.y);
            __half h2 = __float2half_rn(v.z), h3 = __float2half_rn(v.w);
            __half l0 = __float2half_rn(v.x - __half2float(h0));
            __half l1 = __float2half_rn(v.y - __half2float(h1));
            __half l2 = __float2half_rn(v.z - __half2float(h2));
            __half l3 = __float2half_rn(v.w - __half2float(h3));
            __half hi4[4] = {h0, h1, h2, h3};
            __half lo4[4] = {l0, l1, l2, l3};
            *(uint2*)(xh + b * 528 + k16 * 8) = *(uint2*)hi4;
            *(uint2*)(xl + b * 528 + k16 * 8) = *(uint2*)lo4;
        }
    };

    float4 xr[4];
    ldg_x(0, xr);
    issue_w(1);
    cvst(xr, 0);
    ldg_x(1, xr);
    CP_WAIT1();
    __syncthreads();

    float acc[2][4] = {{0.f,0.f,0.f,0.f},{0.f,0.f,0.f,0.f}};
    const int kw = warp * 32;

    for (int c = 0; c < 4; c++) {
        const __half* wh = (const __half*)(sm + ((c & 1) ? WH1_OFF : WH0_OFF));
        const __half* wl = (const __half*)(sm + ((c & 1) ? WL1_OFF : WL0_OFF));
        const __half* xh = (const __half*)(sm + ((c & 1) ? XHI1_OFF : XHI0_OFF));
        const __half* xl = (const __half*)(sm + ((c & 1) ? XLO1_OFF : XLO0_OFF));
#pragma unroll
        for (int s = 0; s < 2; s++) {
            int kl = kw + s * 16 + q4 * 2;
            uint32_t ah0 = *(const uint32_t*)(wh + r * 264 + kl);
            uint32_t ah1 = *(const uint32_t*)(wh + (r + 8) * 264 + kl);
            uint32_t ah2 = *(const uint32_t*)(wh + r * 264 + kl + 8);
            uint32_t ah3 = *(const uint32_t*)(wh + (r + 8) * 264 + kl + 8);
            uint32_t al0 = *(const uint32_t*)(wl + r * 264 + kl);
            uint32_t al1 = *(const uint32_t*)(wl + (r + 8) * 264 + kl);
            uint32_t al2 = *(const uint32_t*)(wl + r * 264 + kl + 8);
            uint32_t al3 = *(const uint32_t*)(wl + (r + 8) * 264 + kl + 8);
#pragma unroll
            for (int nbi = 0; nbi < 2; nbi++) {
                const __half* bx = xh + (nbi * 8 + r) * 264;
                const __half* by = xl + (nbi * 8 + r) * 264;
                uint32_t bh0 = *(const uint32_t*)(bx + kl);
                uint32_t bh1 = *(const uint32_t*)(bx + kl + 8);
                uint32_t bl0 = *(const uint32_t*)(by + kl);
                uint32_t bl1 = *(const uint32_t*)(by + kl + 8);
                mma16816(acc[nbi], ah0, ah1, ah2, ah3, bh0, bh1);
                mma16816(acc[nbi], ah0, ah1, ah2, ah3, bl0, bl1);
                mma16816(acc[nbi], al0, al1, al2, al3, bh0, bh1);
            }
        }
        if (c + 1 < 4) {
            __syncthreads();
            if (c + 2 < 4) issue_w(c + 2);
            cvst(xr, (c + 1) & 1);
            if (c + 2 < 4) { ldg_x(c + 2, xr); CP_WAIT1(); }
            else           { CP_WAIT0(); }
            __syncthreads();
        }
    }

#pragma unroll
    for (int nbi = 0; nbi < 2; nbi++) {
        int col = nbi * 8 + q4 * 2;
        red[warp * 272 + r * 17 + col]           = acc[nbi][0];
        red[warp * 272 + r * 17 + col + 1]       = acc[nbi][1];
        red[warp * 272 + (r + 8) * 17 + col]     = acc[nbi][2];
        red[warp * 272 + (r + 8) * 17 + col + 1] = acc[nbi][3];
    }
    __syncthreads();
    if (tid < 64) {
        int u = tid >> 4, b = tid & 15;
#pragma unroll
        for (int g = 0; g < 4; g++) {
            int row = u * 4 + g;
            float s = 0.f;
#pragma unroll
            for (int w = 0; w < 8; w++) s += red[w * 272 + row * 17 + b];
            g_gH[blockIdx.x * 256 + row * 16 + b] = s;
        }
    }
}

// ---------------------------------------------------------------------
// k_lstmX: gates = Wih_split @ emb[tok] + g_gH + bias; pointwise (plain launch).
__global__ void __launch_bounds__(K1_THREADS)
k_lstmX(int t, const float* __restrict__ emb) {
    extern __shared__ char sm[];
    const uint32_t smem_base = smem_u32(sm);
    int*   tok_s = (int*)(sm + TOK_OFF);
    float* red   = (float*)(sm + RED_OFF);

    const int tid = threadIdx.x, warp = tid >> 5, lane = tid & 31;
    const int r = lane >> 2, q4 = lane & 3;
    const int pr = t & 1, cur = (t + 1) & 1;

    auto issue_w = [&](int c) {
        uint32_t wh = smem_base + ((c & 1) ? WH1_OFF : WH0_OFF);
        uint32_t wl = smem_base + ((c & 1) ? WL1_OFF : WL0_OFF);
#pragma unroll
        for (int q = 0; q < 2; q++) {
            int i = tid + q * 256;
            int row = i >> 5, col16 = i & 31;
            size_t src = (size_t)(blockIdx.x * 16 + row) * KK + c * 256 + col16 * 8;
            CP16(wh + (uint32_t)(row * 528 + col16 * 16), g_Whi + src);
            CP16(wl + (uint32_t)(row * 528 + col16 * 16), g_Wlo + src);
        }
        CP_COMMIT();
    };

    issue_w(0);

    if (tid < BB) tok_s[tid] = (int)(~(unsigned)g_amax[pr][tid]);
    if (blockIdx.x == 0 && tid < BB) { g_amax[cur][tid] = 0ull; g_approx[cur][tid] = 0u; }
    __syncthreads();

    auto ldg_x = [&](int c, float4* xr) {
#pragma unroll
        for (int q = 0; q < 4; q++) {
            int i4 = tid + q * 256;
            int b = i4 >> 6, k16 = i4 & 63;
            xr[q] = *(const float4*)(emb + (size_t)tok_s[b] * EE + c * 256 + k16 * 4);
        }
    };
    auto cvst = [&](const float4* xr, int buf) {
        char* xh = sm + (buf ? XHI1_OFF : XHI0_OFF);
        char* xl = sm + (buf ? XLO1_OFF : XLO0_OFF);
#pragma unroll
        for (int q = 0; q < 4; q++) {
            int i4 = tid + q * 256;
            int b = i4 >> 6, k16 = i4 & 63;
            float4 v = xr[q];
            __half h0 = __float2half_rn(v.x), h1 = __float2half_rn(v.y);
            __half h2 = __float2half_rn(v.z), h3 = __float2half_rn(v.w);
            __half l0 = __float2half_rn(v.x - __half2float(h0));
            __half l1 = __float2half_rn(v.y - __half2float(h1));
            __half l2 = __float2half_rn(v.z - __half2float(h2));
            __half l3 = __float2half_rn(v.w - __half2float(h3));
            __half hi4[4] = {h0, h1, h2, h3};
            __half lo4[4] = {l0, l1, l2, l3};
            *(uint2*)(xh + b * 528 + k16 * 8) = *(uint2*)hi4;
            *(uint2*)(xl + b * 528 + k16 * 8) = *(uint2*)lo4;
        }
    };

    float4 xr[4];
    ldg_x(0, xr);
    issue_w(1);
    cvst(xr, 0);
    ldg_x(1, xr);
    CP_WAIT1();
    __syncthreads();

    float acc[2][4] = {{0.f,0.f,0.f,0.f},{0.f,0.f,0.f,0.f}};
    const int kw = warp * 32;

    for (int c = 0; c < 4; c++) {
        const __half* wh = (const __half*)(sm + ((c & 1) ? WH1_OFF : WH0_OFF));
        const __half* wl = (const __half*)(sm + ((c & 1) ? WL1_OFF : WL0_OFF));
        const __half* xh = (const __half*)(sm + ((c & 1) ? XHI1_OFF : XHI0_OFF));
        const __half* xl = (const __half*)(sm + ((c & 1) ? XLO1_OFF : XLO0_OFF));
#pragma unroll
        for (int s = 0; s < 2; s++) {
            int kl = kw + s * 16 + q4 * 2;
            uint32_t ah0 = *(const uint32_t*)(wh + r * 264 + kl);
            uint32_t ah1 = *(const uint32_t*)(wh + (r + 8) * 264 + kl);
            uint32_t ah2 = *(const uint32_t*)(wh + r * 264 + kl + 8);
            uint32_t ah3 = *(const uint32_t*)(wh + (r + 8) * 264 + kl + 8);
            uint32_t al0 = *(const uint32_t*)(wl + r * 264 + kl);
            uint32_t al1 = *(const uint32_t*)(wl + (r + 8) * 264 + kl);
            uint32_t al2 = *(const uint32_t*)(wl + r * 264 + kl + 8);
            uint32_t al3 = *(const uint32_t*)(wl + (r + 8) * 264 + kl + 8);
#pragma unroll
            for (int nbi = 0; nbi < 2; nbi++) {
                const __half* bx = xh + (nbi * 8 + r) * 264;
                const __half* by = xl + (nbi * 8 + r) * 264;
                uint32_t bh0 = *(const uint32_t*)(bx + kl);
                uint32_t bh1 = *(const uint32_t*)(bx + kl + 8);
                uint32_t bl0 = *(const uint32_t*)(by + kl);
                uint32_t bl1 = *(const uint32_t*)(by + kl + 8);
                mma16816(acc[nbi], ah0, ah1, ah2, ah3, bh0, bh1);
                mma16816(acc[nbi], ah0, ah1, ah2, ah3, bl0, bl1);
                mma16816(acc[nbi], al0, al1, al2, al3, bh0, bh1);
            }
        }
        if (c + 1 < 4) {
            __syncthreads();
            if (c + 2 < 4) issue_w(c + 2);
            cvst(xr, (c + 1) & 1);
            if (c + 2 < 4) { ldg_x(c + 2, xr); CP_WAIT1(); }
            else           { CP_WAIT0(); }
            __syncthreads();
        }
    }

#pragma unroll
    for (int nbi = 0; nbi < 2; nbi++) {
        int col = nbi * 8 + q4 * 2;
        red[warp * 272 + r * 17 + col]           = acc[nbi][0];
        red[warp * 272 + r * 17 + col + 1]       = acc[nbi][1];
        red[warp * 272 + (r + 8) * 17 + col]     = acc[nbi][2];
        red[warp * 272 + (r + 8) * 17 + col + 1] = acc[nbi][3];
    }
    __syncthreads();
    if (tid < 64) {
        int u = tid >> 4, b = tid & 15;
        float gv[4];
#pragma unroll
        for (int g = 0; g < 4; g++) {
            int row = u * 4 + g;
            float s = g_pb[blockIdx.x * 16 + row] + g_gH[blockIdx.x * 256 + row * 16 + b];
#pragma unroll
            for (int w = 0; w < 8; w++) s += red[w * 272 + row * 17 + b];
            gv[g] = s;
        }
        int j = blockIdx.x * 4 + u;
        float si = 1.f / (1.f + expf(-gv[0]));
        float sf = 1.f / (1.f + expf(-gv[1]));
        float so = 1.f / (1.f + expf(-gv[3]));
        float cc = sf * g_c[b * HH + j] + si * tanhf(gv[2]);
        g_c[b * HH + j] = cc;
        float h = so * tanhf(cc);
        g_h[cur][b * HH + j] = h;
        g_h16[b * HH + j] = __float2half(h);
    }
}

// ---------------------------------------------------------------------
// K2 v4: W fragments loaded straight to registers via coalesced LDG.128
// from the fragment-packed g_WF. No smem W, no barriers in the main loop.
__global__ void __launch_bounds__(K2_THREADS)
k_logits(int t, const float* __restrict__ Wlin, const float* __restrict__ blin,
         float* __restrict__ out) {
    extern __shared__ char sm[];
    __half* h_s   = (__half*)(sm + H_OFF);
    float*  log_s = (float*)(sm + LOG_OFF);
    float*  thr_s = (float*)(sm + THR_OFF);
    int*    cnt_s = (int*)(sm + CNT_OFF);
    int*    cand_s = (int*)(sm + CAND_OFF);

    const int tid = threadIdx.x, warp = tid >> 5, lane = tid & 31;
    const int cur = (t + 1) & 1;
    const int r = lane >> 2, q4 = lane & 3;

    const char* wbase = (const char*)g_WF
                      + (size_t)blockIdx.x * (NCHUNK * 16384) + (size_t)tid * 16;
    auto pf = [&](int c, uint4* wr) {
#pragma unroll
        for (int ks = 0; ks < 4; ks++)
            wr[ks] = *(const uint4*)(wbase + c * 16384 + ks * 4096);
    };

    // ---- PDL prelude: W prefetch is h-independent ----
    uint4 wr0[4], wr1[4];
    pf(0, wr0);
    pf(1, wr1);
    cudaGridDependencySynchronize();
    cudaTriggerProgrammaticLaunchCompletion();

    if (tid == 0) *cnt_s = 0;
#pragma unroll
    for (int q = 0; q < 8; q++) {
        int i = tid + q * 256;
        int b = i >> 7, k8 = i & 127;
        float4 v = *(const float4*)(g_h16 + (size_t)b * HH + k8 * 8);
        *(float4*)(h_s + b * HPAD + k8 * 8) = v;
    }
    __syncthreads();

    float acc0[4] = {0.f, 0.f, 0.f, 0.f};
    float acc1[4] = {0.f, 0.f, 0.f, 0.f};

#pragma unroll
    for (int cc = 0; cc < NCHUNK; cc += 2) {
        // even chunk: wr0
#pragma unroll
        for (int ks = 0; ks < 4; ks++) {
            int kg = cc * 64 + ks * 16 + q4 * 2;
            uint32_t b00 = *(const uint32_t*)(h_s + r * HPAD + kg);
            uint32_t b01 = *(const uint32_t*)(h_s + r * HPAD + kg + 8);
            uint32_t b10 = *(const uint32_t*)(h_s + (r + 8) * HPAD + kg);
            uint32_t b11 = *(const uint32_t*)(h_s + (r + 8) * HPAD + kg + 8);
            mma16816(acc0, wr0[ks].x, wr0[ks].y, wr0[ks].z, wr0[ks].w, b00, b01);
            mma16816(acc1, wr0[ks].x, wr0[ks].y, wr0[ks].z, wr0[ks].w, b10, b11);
        }
        if (cc + 2 < NCHUNK) pf(cc + 2, wr0);
        // odd chunk: wr1
#pragma unroll
        for (int ks = 0; ks < 4; ks++) {
            int kg = (cc + 1) * 64 + ks * 16 + q4 * 2;
            uint32_t b00 = *(const uint32_t*)(h_s + r * HPAD + kg);
            uint32_t b01 = *(const uint32_t*)(h_s + r * HPAD + kg + 8);
            uint32_t b10 = *(const uint32_t*)(h_s + (r + 8) * HPAD + kg);
            uint32_t b11 = *(const uint32_t*)(h_s + (r + 8) * HPAD + kg + 8);
            mma16816(acc0, wr1[ks].x, wr1[ks].y, wr1[ks].z, wr1[ks].w, b00, b01);
            mma16816(acc1, wr1[ks].x, wr1[ks].y, wr1[ks].z, wr1[ks].w, b10, b11);
        }
        if (cc + 3 < NCHUNK) pf(cc + 3, wr1);
    }

    {
        const int rbase = warp * 16 + r;
        const float bl0 = blin[blockIdx.x * K2_ROWS + rbase];
        const float bl1 = blin[blockIdx.x * K2_ROWS + rbase + 8];
        const int c0 = q4 * 2;
        log_s[rbase * LPAD + c0]           = acc0[0] + bl0;
        log_s[rbase * LPAD + c0 + 1]       = acc0[1] + bl0;
        log_s[(rbase + 8) * LPAD + c0]     = acc0[2] + bl1;
        log_s[(rbase + 8) * LPAD + c0 + 1] = acc0[3] + bl1;
        log_s[rbase * LPAD + c0 + 8]       = acc1[0] + bl0;
        log_s[rbase * LPAD + c0 + 9]       = acc1[1] + bl0;
        log_s[(rbase + 8) * LPAD + c0 + 8] = acc1[2] + bl1;
        log_s[(rbase + 8) * LPAD + c0 + 9] = acc1[3] + bl1;
    }
    __syncthreads();

#pragma unroll
    for (int i = 0; i < 8; i++) {
        int idx = tid + i * 256;
        int row = idx & 127, b = idx >> 7;
        out[(size_t)b * TT * VV + (size_t)t * VV + blockIdx.x * K2_ROWS + row] =
            log_s[row * LPAD + b];
    }

    {
        int b = 2 * warp + (lane >> 4);
        int l = lane & 15;
        float s = 0.f, m = -1e30f;
#pragma unroll
        for (int rr = 0; rr < 8; rr++) {
            float v = log_s[(l * 8 + rr) * LPAD + b];
            s += expf(v);
            m = fmaxf(m, v);
        }
#pragma unroll
        for (int off = 8; off; off >>= 1) {
            s += __shfl_xor_sync(0xFFFFFFFFu, s, off);
            m = fmaxf(m, __shfl_xor_sync(0xFFFFFFFFu, m, off));
        }
        if (l == 0) {
            g_pexp[t][b][blockIdx.x] = s;
            unsigned fm = ford(m);
            unsigned old = atomicMax(&g_approx[cur][b], fm);
            unsigned L = old > fm ? old : fm;
            thr_s[b] = funord(L) - TAU;
        }
    }
    __syncthreads();

#pragma unroll
    for (int i = 0; i < 8; i++) {
        int idx = tid + i * 256;
        int row = idx & 127, b = idx >> 7;
        if (log_s[row * LPAD + b] >= thr_s[b]) {
            int slot = atomicAdd(cnt_s, 1);
            if (slot < 128) cand_s[slot] = ((blockIdx.x * K2_ROWS + row) << 4) | b;
        }
    }
    __syncthreads();

    int n = *cnt_s; if (n > 128) n = 128;
    for (int e = warp; e < n; e += 8) {
        int pk = cand_s[e];
        int rr = pk >> 4, b = pk & 15;
        const float4* Wr = (const float4*)(Wlin + (size_t)rr * HH);
        const float4* hr = (const float4*)(g_h[cur] + b * HH);
        float acc = 0.f;
#pragma unroll
        for (int qq = 0; qq < 8; qq++) {
            float4 w = Wr[lane + qq * 32];
            float4 h = hr[lane + qq * 32];
            acc += w.x * h.x + w.y * h.y + w.z * h.z + w.w * h.w;
        }
#pragma unroll
        for (int off = 16; off; off >>= 1) acc += __shfl_xor_sync(0xFFFFFFFFu, acc, off);
        if (lane == 0) {
            float ex = acc + blin[rr];
            unsigned long long pkd =
                ((unsigned long long)ford(ex) << 32) | (unsigned)(~(unsigned)rr);
            atomicMax(&g_amax[cur][b], pkd);
        }
    }
}

// ---------------------------------------------------------------------
__global__ void k_final(float* __restrict__ out) {
    const int t = blockIdx.x >> 4;
    const int b = blockIdx.x & 15;
    __shared__ float red[256];
    float s = 0.f;
    for (int i = threadIdx.x; i < K2_BLOCKS; i += 256) s += g_pexp[t][b][i];
    red[threadIdx.x] = s;
    __syncthreads();
    for (int off = 128; off; off >>= 1) {
        if (threadIdx.x < off) red[threadIdx.x] += red[threadIdx.x + off];
        __syncthreads();
    }
    const float lse = logf(red[0]);
    float* p = out + (size_t)b * TT * VV + (size_t)t * VV;
    for (int i = threadIdx.x; i < VV / 4; i += 256) {
        float4 v = *(float4*)(p + i * 4);
        v.x -= lse; v.y -= lse; v.z -= lse; v.w -= lse;
        *(float4*)(p + i * 4) = v;
    }
}

__global__ void k_hc(float* __restrict__ out) {
    int i = blockIdx.x * blockDim.x + threadIdx.x;
    if (i < BB * HH) {
        out[(size_t)BB * TT * VV + i]           = g_h[0][i];
        out[(size_t)BB * TT * VV + BB * HH + i] = g_c[i];
    }
}

// ---------------------------------------------------------------------
extern "C" void kernel_launch(void* const* d_in, const int* in_sizes, int n_in,
                              void* d_out, int out_size) {
    const float* h0   = (const float*)d_in[1];
    const float* c0   = (const float*)d_in[2];
    const float* emb  = (const float*)d_in[3];
    const float* Wih  = (const float*)d_in[4];
    const float* Whh  = (const float*)d_in[5];
    const float* bih  = (const float*)d_in[6];
    const float* bhh  = (const float*)d_in[7];
    const float* Wlin = (const float*)d_in[8];
    const float* blin = (const float*)d_in[9];
    float* out = (float*)d_out;

    cudaFuncSetAttribute(k_lstmX,  cudaFuncAttributeMaxDynamicSharedMemorySize, K1_SMEM);
    cudaFuncSetAttribute(k_gemmH,  cudaFuncAttributeMaxDynamicSharedMemorySize, K1_SMEM);
    cudaFuncSetAttribute(k_logits, cudaFuncAttributeMaxDynamicSharedMemorySize, K2_SMEM);

    cudaLaunchAttribute pdl[1];
    pdl[0].id = cudaLaunchAttributeProgrammaticStreamSerialization;
    pdl[0].val.programmaticStreamSerializationAllowed = 1;

    k_init<<<(BB * HH + 255) / 256, 256>>>(h0, c0, bih, bhh);
    k_cvtF<<<(K2_BLOCKS * NCHUNK * 4 * 256) / 256, 256>>>(Wlin);
    k_cvt2<<<(int)((size_t)4 * HH * KK / 8 / 256), 256>>>(Wih, Whh);

    k_gemmH<<<K1_BLOCKS, K1_THREADS, K1_SMEM>>>(0);

    for (int t = 0; t < TT; t++) {
        k_lstmX<<<K1_BLOCKS, K1_THREADS, K1_SMEM>>>(t, emb);

        if (t < TT - 1) {
            cudaLaunchConfig_t cfg = {};
            cfg.gridDim = dim3(K1_BLOCKS); cfg.blockDim = dim3(K1_THREADS);
            cfg.dynamicSmemBytes = K1_SMEM; cfg.stream = 0;
            cfg.attrs = pdl; cfg.numAttrs = 1;
            cudaLaunchKernelEx(&cfg, k_gemmH, t + 1);
        }
        {
            cudaLaunchConfig_t cfg = {};
            cfg.gridDim = dim3(K2_BLOCKS); cfg.blockDim = dim3(K2_THREADS);
            cfg.dynamicSmemBytes = K2_SMEM; cfg.stream = 0;
            cfg.attrs = pdl; cfg.numAttrs = 1;
            cudaLaunchKernelEx(&cfg, k_logits, t, Wlin, blin, out);
        }
    }
    k_final<<<TT * BB, 256>>>(out);
    k_hc<<<(BB * HH + 255) / 256, 256>>>(out);
}